// round 1
// baseline (speedup 1.0000x reference)
#include <cuda_runtime.h>
#include <math.h>

#define DIMC 512
#define NHD  8
#define HDD  64
#define BB   8
#define NN   1024
#define MTOT (BB*NN)   // 8192

// Scratch (allocation-free): q/k/v in [b][h][n][d] layout, attention out in [b][n][c]
__device__ float g_q[BB*NHD*NN*HDD];
__device__ float g_k[BB*NHD*NN*HDD];
__device__ float g_v[BB*NHD*NN*HDD];
__device__ float g_o[MTOT*DIMC];

// ---------------------------------------------------------------------------
// GEMM: C[M,NC] = A[M,512] @ W[NC,512]^T
// MODE 0: A = x, scatter-write into g_q/g_k/g_v   (NC = 1536)
// MODE 1: A = g_o, plain write into Cout (d_out)  (NC = 512)
// 64x64 tile, BK=16, 256 threads, 4x4 microtile
// ---------------------------------------------------------------------------
template<int MODE>
__global__ __launch_bounds__(256, 2)
void gemm_k(const float* __restrict__ Ain,
            const float* __restrict__ Wm,
            float* __restrict__ Cout)
{
    __shared__ float As[16][64];
    __shared__ float Bs[16][64];
    const float* A = (MODE == 1) ? (const float*)g_o : Ain;
    const int KD = DIMC;
    const int m0 = blockIdx.y << 6;
    const int n0 = blockIdx.x << 6;
    const int tid = threadIdx.x;
    const int ty = tid >> 4, tx = tid & 15;
    const int lr = tid >> 2;            // 0..63 row/col within tile
    const int lq = (tid & 3) << 2;      // k-quad

    const float* aptr = A  + (size_t)(m0 + lr) * KD + lq;
    const float* bptr = Wm + (size_t)(n0 + lr) * KD + lq;

    float acc[4][4];
#pragma unroll
    for (int i = 0; i < 4; i++)
#pragma unroll
        for (int j = 0; j < 4; j++) acc[i][j] = 0.f;

    for (int k0 = 0; k0 < KD; k0 += 16) {
        float4 av = *(const float4*)(aptr + k0);
        float4 bv = *(const float4*)(bptr + k0);
        As[lq+0][lr] = av.x; As[lq+1][lr] = av.y;
        As[lq+2][lr] = av.z; As[lq+3][lr] = av.w;
        Bs[lq+0][lr] = bv.x; Bs[lq+1][lr] = bv.y;
        Bs[lq+2][lr] = bv.z; Bs[lq+3][lr] = bv.w;
        __syncthreads();
#pragma unroll
        for (int k = 0; k < 16; k++) {
            float4 a = *(const float4*)(&As[k][ty << 2]);
            float4 b = *(const float4*)(&Bs[k][tx << 2]);
            float ar[4] = {a.x, a.y, a.z, a.w};
            float br[4] = {b.x, b.y, b.z, b.w};
#pragma unroll
            for (int i = 0; i < 4; i++)
#pragma unroll
                for (int j = 0; j < 4; j++)
                    acc[i][j] = fmaf(ar[i], br[j], acc[i][j]);
        }
        __syncthreads();
    }

    if (MODE == 0) {
        // column c in [0,1536): which = c/512, h = (c/64)%8, d = c%64.
        // A 64-wide tile never crosses which/h boundaries.
        const int which = n0 >> 9;
        const int h = (n0 >> 6) & (NHD - 1);
        float* dst = (which == 0) ? g_q : ((which == 1) ? g_k : g_v);
#pragma unroll
        for (int i = 0; i < 4; i++) {
            int gm = m0 + (ty << 2) + i;
            int b = gm >> 10;
            int n = gm & (NN - 1);
            float* row = dst + ((size_t)((b * NHD + h) * NN + n)) * HDD + (tx << 2);
            *(float4*)row = make_float4(acc[i][0], acc[i][1], acc[i][2], acc[i][3]);
        }
    } else {
#pragma unroll
        for (int i = 0; i < 4; i++) {
            float* row = Cout + (size_t)(m0 + (ty << 2) + i) * DIMC + n0 + (tx << 2);
            *(float4*)row = make_float4(acc[i][0], acc[i][1], acc[i][2], acc[i][3]);
        }
    }
}

// ---------------------------------------------------------------------------
// Flash-style attention with analytic spatial-decay bias.
// Block = (b,h, 64-query tile), 256 threads. Key loop in tiles of 32.
// Each thread owns 2 query rows x (4 S-cols / 8 O-dims).
// ---------------------------------------------------------------------------
__global__ __launch_bounds__(256, 1)
void attn_k(const float* __restrict__ logd, const int* __restrict__ pW)
{
    __shared__ float Qs[HDD][66];   // [d][m], padded (2-way store conflicts max)
    __shared__ float Ks[HDD][36];   // [d][j], padded, rows 16B-aligned for float4
    __shared__ float Vs[32][HDD];   // [j][d], natural
    __shared__ float Ss[64][33];    // scores/probs, padded for row scans
    __shared__ float m_s[64], l_s[64], al_s[64];
    __shared__ float kr_s[32], kc_s[32];
    __shared__ float decay_sh;

    const int bh = blockIdx.y;
    const int b = bh >> 3, h = bh & 7;
    const int q0 = blockIdx.x << 6;
    const int tid = threadIdx.x;
    const int Wg = pW ? *pW : 32;

    const size_t base = (size_t)(b * NHD + h) * NN * HDD;
    const float* qb = g_q + base;
    const float* kb = g_k + base;
    const float* vb = g_v + base;

    for (int i = tid; i < 64 * HDD; i += 256) {
        int m = i >> 6, d = i & 63;
        Qs[d][m] = qb[(size_t)(q0 + m) * HDD + d];
    }
    if (tid < 64) { m_s[tid] = -1e30f; l_s[tid] = 0.f; }
    if (tid == 0) decay_sh = log1pf(expf(logd[h]));   // softplus
    __syncthreads();

    const float decay = decay_sh;
    const int ty = tid >> 3;            // 0..31
    const int tx = tid & 7;             // 0..7
    const int r0 = ty << 1, r1 = r0 + 1;
    const float qr0 = (float)((q0 + r0) / Wg), qc0 = (float)((q0 + r0) % Wg);
    const float qr1 = (float)((q0 + r1) / Wg), qc1 = (float)((q0 + r1) % Wg);

    float acc0[8], acc1[8];
#pragma unroll
    for (int d = 0; d < 8; d++) { acc0[d] = 0.f; acc1[d] = 0.f; }
    const float scale = 0.125f;         // hd^-0.5, hd = 64

    for (int t = 0; t < NN / 32; t++) {
        const int k0 = t << 5;
        for (int i = tid; i < 32 * HDD; i += 256) {
            int j = i >> 6, d = i & 63;
            Ks[d][j] = kb[(size_t)(k0 + j) * HDD + d];
            Vs[j][d] = vb[(size_t)(k0 + j) * HDD + d];
        }
        if (tid < 32) {
            kr_s[tid] = (float)((k0 + tid) / Wg);
            kc_s[tid] = (float)((k0 + tid) % Wg);
        }
        __syncthreads();

        // ---- S = Q K^T (2 rows x 4 cols per thread) ----
        float s0[4] = {0.f, 0.f, 0.f, 0.f};
        float s1[4] = {0.f, 0.f, 0.f, 0.f};
#pragma unroll 16
        for (int d = 0; d < HDD; d++) {
            float a0 = Qs[d][r0];
            float a1 = Qs[d][r1];
            float4 bv = *(const float4*)(&Ks[d][tx << 2]);
            s0[0] = fmaf(a0, bv.x, s0[0]); s0[1] = fmaf(a0, bv.y, s0[1]);
            s0[2] = fmaf(a0, bv.z, s0[2]); s0[3] = fmaf(a0, bv.w, s0[3]);
            s1[0] = fmaf(a1, bv.x, s1[0]); s1[1] = fmaf(a1, bv.y, s1[1]);
            s1[2] = fmaf(a1, bv.z, s1[2]); s1[3] = fmaf(a1, bv.w, s1[3]);
        }
#pragma unroll
        for (int j = 0; j < 4; j++) {
            int kj = (tx << 2) + j;
            float d0 = fabsf(qr0 - kr_s[kj]) + fabsf(qc0 - kc_s[kj]);
            float d1 = fabsf(qr1 - kr_s[kj]) + fabsf(qc1 - kc_s[kj]);
            Ss[r0][kj] = fmaf(s0[j], scale, -decay * d0);
            Ss[r1][kj] = fmaf(s1[j], scale, -decay * d1);
        }
        __syncthreads();

        // ---- online softmax stats (1 thread per query row) ----
        if (tid < 64) {
            float mo = m_s[tid];
            float mx = mo;
#pragma unroll
            for (int j = 0; j < 32; j++) mx = fmaxf(mx, Ss[tid][j]);
            float alpha = __expf(mo - mx);    // first tile: exp(-huge) -> 0
            float l = l_s[tid] * alpha;
#pragma unroll
            for (int j = 0; j < 32; j++) {
                float p = __expf(Ss[tid][j] - mx);
                Ss[tid][j] = p;
                l += p;
            }
            m_s[tid] = mx; l_s[tid] = l; al_s[tid] = alpha;
        }
        __syncthreads();

        // ---- rescale + O += P V (2 rows x 8 dims per thread) ----
        const float al0 = al_s[r0], al1 = al_s[r1];
#pragma unroll
        for (int d = 0; d < 8; d++) { acc0[d] *= al0; acc1[d] *= al1; }
#pragma unroll 8
        for (int j = 0; j < 32; j++) {
            float p0 = Ss[r0][j], p1 = Ss[r1][j];
            float4 va = *(const float4*)(&Vs[j][tx << 3]);
            float4 vb4 = *(const float4*)(&Vs[j][(tx << 3) + 4]);
            acc0[0] = fmaf(p0, va.x,  acc0[0]); acc0[1] = fmaf(p0, va.y,  acc0[1]);
            acc0[2] = fmaf(p0, va.z,  acc0[2]); acc0[3] = fmaf(p0, va.w,  acc0[3]);
            acc0[4] = fmaf(p0, vb4.x, acc0[4]); acc0[5] = fmaf(p0, vb4.y, acc0[5]);
            acc0[6] = fmaf(p0, vb4.z, acc0[6]); acc0[7] = fmaf(p0, vb4.w, acc0[7]);
            acc1[0] = fmaf(p1, va.x,  acc1[0]); acc1[1] = fmaf(p1, va.y,  acc1[1]);
            acc1[2] = fmaf(p1, va.z,  acc1[2]); acc1[3] = fmaf(p1, va.w,  acc1[3]);
            acc1[4] = fmaf(p1, vb4.x, acc1[4]); acc1[5] = fmaf(p1, vb4.y, acc1[5]);
            acc1[6] = fmaf(p1, vb4.z, acc1[6]); acc1[7] = fmaf(p1, vb4.w, acc1[7]);
        }
        __syncthreads();
    }

    const float inv0 = 1.f / l_s[r0];
    const float inv1 = 1.f / l_s[r1];
    float* o0 = g_o + (size_t)(b * NN + q0 + r0) * DIMC + h * HDD + (tx << 3);
    float* o1 = g_o + (size_t)(b * NN + q0 + r1) * DIMC + h * HDD + (tx << 3);
    *(float4*)(o0)     = make_float4(acc0[0]*inv0, acc0[1]*inv0, acc0[2]*inv0, acc0[3]*inv0);
    *(float4*)(o0 + 4) = make_float4(acc0[4]*inv0, acc0[5]*inv0, acc0[6]*inv0, acc0[7]*inv0);
    *(float4*)(o1)     = make_float4(acc1[0]*inv1, acc1[1]*inv1, acc1[2]*inv1, acc1[3]*inv1);
    *(float4*)(o1 + 4) = make_float4(acc1[4]*inv1, acc1[5]*inv1, acc1[6]*inv1, acc1[7]*inv1);
}

// ---------------------------------------------------------------------------
extern "C" void kernel_launch(void* const* d_in, const int* in_sizes, int n_in,
                              void* d_out, int out_size)
{
    const float* x      = (const float*)d_in[0];
    const float* w_qkv  = (const float*)d_in[1];
    const float* w_proj = (const float*)d_in[2];
    const float* logd   = (const float*)d_in[3];
    const int*   pW     = (n_in > 5) ? (const int*)d_in[5] : nullptr;
    float* out = (float*)d_out;

    dim3 blk(256);
    // qkv projection: [8192,512] @ [512,1536]^T -> scatter to q/k/v
    gemm_k<0><<<dim3(24, 128), blk>>>(x, w_qkv, nullptr);
    // spatial-decay attention
    attn_k<<<dim3(16, 64), blk>>>(logd, pW);
    // output projection: [8192,512] @ [512,512]^T -> d_out
    gemm_k<1><<<dim3(8, 128), blk>>>(nullptr, w_proj, out);
}

// round 6
// speedup vs baseline: 1.1600x; 1.1600x over previous
#include <cuda_runtime.h>
#include <cuda_bf16.h>
#include <cstdint>
#include <math.h>

#define DIMC 512
#define NHD  8
#define HDD  64
#define BB   8
#define NN   1024
#define MTOT (BB*NN)   // 8192

// ---------------- scratch (allocation-free) ----------------
__device__ float g_q[BB*NHD*NN*HDD];
__device__ float g_k[BB*NHD*NN*HDD];
__device__ float g_v[BB*NHD*NN*HDD];
__device__ float g_o[MTOT*DIMC];
__device__ __nv_bfloat16 gx_hi[MTOT*DIMC],  gx_lo[MTOT*DIMC];
__device__ __nv_bfloat16 gwq_hi[3*DIMC*DIMC], gwq_lo[3*DIMC*DIMC];
__device__ __nv_bfloat16 gwp_hi[DIMC*DIMC],  gwp_lo[DIMC*DIMC];
__device__ __nv_bfloat16 go_hi[MTOT*DIMC],  go_lo[MTOT*DIMC];

// ---------------- fp32 -> bf16 hi/lo split ----------------
// DST selects destination (and for DST=3, source) INSIDE device code.
// Never pass __device__ symbols as host-side kernel args (host shadow
// address + GB300 ATS = silent writes to host memory).
template<int DST>
__global__ void cvt_k(const float* __restrict__ s, int n)
{
    __nv_bfloat16* hi;
    __nv_bfloat16* lo;
    if (DST == 0)      { hi = gx_hi;  lo = gx_lo;  }
    else if (DST == 1) { hi = gwq_hi; lo = gwq_lo; }
    else if (DST == 2) { hi = gwp_hi; lo = gwp_lo; }
    else               { hi = go_hi;  lo = go_lo;  s = g_o; }

    int i = (blockIdx.x * blockDim.x + threadIdx.x) * 4;
    if (i >= n) return;
    float4 v = *(const float4*)(s + i);
    __nv_bfloat16 h0 = __float2bfloat16(v.x);
    __nv_bfloat16 h1 = __float2bfloat16(v.y);
    __nv_bfloat16 h2 = __float2bfloat16(v.z);
    __nv_bfloat16 h3 = __float2bfloat16(v.w);
    __nv_bfloat162 hp0; hp0.x = h0; hp0.y = h1;
    __nv_bfloat162 hp1; hp1.x = h2; hp1.y = h3;
    __nv_bfloat162 lp0;
    lp0.x = __float2bfloat16(v.x - __bfloat162float(h0));
    lp0.y = __float2bfloat16(v.y - __bfloat162float(h1));
    __nv_bfloat162 lp1;
    lp1.x = __float2bfloat16(v.z - __bfloat162float(h2));
    lp1.y = __float2bfloat16(v.w - __bfloat162float(h3));
    *(__nv_bfloat162*)(hi + i)     = hp0;
    *(__nv_bfloat162*)(hi + i + 2) = hp1;
    *(__nv_bfloat162*)(lo + i)     = lp0;
    *(__nv_bfloat162*)(lo + i + 2) = lp1;
}

// ---------------------------------------------------------------------------
// HMMA GEMM via mma.sync m16n8k16 bf16 (baseline PTX; tensor pipe).
// C[M,NC] = A[M,512] @ W[NC,512]^T, split-bf16 3 passes:
//   C = Ah Bh + Al Bh + Ah Bl
// Block tile 128x64, 8 warps (4 m x 2 n), warp tile 32x32, K-chunk 32 in smem.
// ---------------------------------------------------------------------------
#define LDA_S 40   // smem row stride in bf16 (32 data + 8 pad) -> conflict-free

__device__ __forceinline__ void mma_bf16(float& c0, float& c1, float& c2, float& c3,
                                         uint32_t a0, uint32_t a1, uint32_t a2, uint32_t a3,
                                         uint32_t b0, uint32_t b1)
{
    asm volatile(
        "mma.sync.aligned.m16n8k16.row.col.f32.bf16.bf16.f32 "
        "{%0,%1,%2,%3}, {%4,%5,%6,%7}, {%8,%9}, {%0,%1,%2,%3};"
        : "+f"(c0), "+f"(c1), "+f"(c2), "+f"(c3)
        : "r"(a0), "r"(a1), "r"(a2), "r"(a3), "r"(b0), "r"(b1));
}

template<int MODE>
__global__ __launch_bounds__(256, 2)
void hgemm_k(float* __restrict__ Cout)
{
    __shared__ __align__(16) __nv_bfloat16 As[128 * LDA_S];
    __shared__ __align__(16) __nv_bfloat16 Bs[64 * LDA_S];

    const int tid = threadIdx.x;
    const int wid = tid >> 5, lane = tid & 31;
    const int g = lane >> 2, t = lane & 3;
    const int m0 = blockIdx.y << 7;
    const int n0 = blockIdx.x << 6;
    const int wm = (wid & 3) << 5;   // warp row offset in tile
    const int wn = (wid >> 2) << 5;  // warp col offset in tile

    const __nv_bfloat16* a_hi = (MODE == 0) ? gx_hi : go_hi;
    const __nv_bfloat16* a_lo = (MODE == 0) ? gx_lo : go_lo;
    const __nv_bfloat16* b_hi = (MODE == 0) ? gwq_hi : gwp_hi;
    const __nv_bfloat16* b_lo = (MODE == 0) ? gwq_lo : gwp_lo;

    float acc[2][4][4];   // [mi][ni][c0..c3]
#pragma unroll
    for (int mi = 0; mi < 2; mi++)
#pragma unroll
        for (int ni = 0; ni < 4; ni++)
#pragma unroll
            for (int c = 0; c < 4; c++) acc[mi][ni][c] = 0.f;

    for (int chunk = 0; chunk < 48; chunk++) {
        const int pass = chunk >> 4;
        const int kc = (chunk & 15) << 5;
        const __nv_bfloat16* asrc = (pass == 1) ? a_lo : a_hi;
        const __nv_bfloat16* bsrc = (pass == 2) ? b_lo : b_hi;

        __syncthreads();
        // A: 128x32 bf16 = 512 uint4; B: 64x32 = 256 uint4
#pragma unroll
        for (int it = 0; it < 2; it++) {
            int idx = tid + (it << 8);
            int row = idx >> 2, cu = idx & 3;
            uint4 v = *(const uint4*)(asrc + (size_t)(m0 + row) * DIMC + kc + cu * 8);
            *(uint4*)(As + row * LDA_S + cu * 8) = v;
        }
        {
            int row = tid >> 2, cu = tid & 3;
            uint4 v = *(const uint4*)(bsrc + (size_t)(n0 + row) * DIMC + kc + cu * 8);
            *(uint4*)(Bs + row * LDA_S + cu * 8) = v;
        }
        __syncthreads();

#pragma unroll
        for (int ks = 0; ks < 2; ks++) {
            const int k0 = ks << 4;
            uint32_t af[2][4];
#pragma unroll
            for (int mi = 0; mi < 2; mi++) {
                const __nv_bfloat16* ab = As + (wm + (mi << 4)) * LDA_S + k0;
                af[mi][0] = *(const uint32_t*)(ab + g * LDA_S + 2 * t);
                af[mi][1] = *(const uint32_t*)(ab + (g + 8) * LDA_S + 2 * t);
                af[mi][2] = *(const uint32_t*)(ab + g * LDA_S + 2 * t + 8);
                af[mi][3] = *(const uint32_t*)(ab + (g + 8) * LDA_S + 2 * t + 8);
            }
#pragma unroll
            for (int ni = 0; ni < 4; ni++) {
                const __nv_bfloat16* bb = Bs + (wn + (ni << 3) + g) * LDA_S + k0;
                uint32_t b0 = *(const uint32_t*)(bb + 2 * t);
                uint32_t b1 = *(const uint32_t*)(bb + 2 * t + 8);
#pragma unroll
                for (int mi = 0; mi < 2; mi++)
                    mma_bf16(acc[mi][ni][0], acc[mi][ni][1],
                             acc[mi][ni][2], acc[mi][ni][3],
                             af[mi][0], af[mi][1], af[mi][2], af[mi][3], b0, b1);
            }
        }
    }

    // -------- epilogue --------
    if (MODE == 0) {
        const int which = n0 >> 9;
        const int h = (n0 >> 6) & (NHD - 1);
        float* dst = (which == 0) ? g_q : ((which == 1) ? g_k : g_v);
#pragma unroll
        for (int mi = 0; mi < 2; mi++)
#pragma unroll
            for (int ni = 0; ni < 4; ni++) {
                int gm = m0 + wm + (mi << 4) + g;
                int d = wn + (ni << 3) + 2 * t;     // 0..63 within head
                int b = gm >> 10, n = gm & (NN - 1);
                float* p0 = dst + ((size_t)((b * NHD + h) * NN + n)) * HDD + d;
                *(float2*)p0 = make_float2(acc[mi][ni][0], acc[mi][ni][1]);
                int gm2 = gm + 8;
                int b2 = gm2 >> 10, n2 = gm2 & (NN - 1);
                float* p1 = dst + ((size_t)((b2 * NHD + h) * NN + n2)) * HDD + d;
                *(float2*)p1 = make_float2(acc[mi][ni][2], acc[mi][ni][3]);
            }
    } else {
#pragma unroll
        for (int mi = 0; mi < 2; mi++)
#pragma unroll
            for (int ni = 0; ni < 4; ni++) {
                int gm = m0 + wm + (mi << 4) + g;
                int cc = n0 + wn + (ni << 3) + 2 * t;
                *(float2*)(Cout + (size_t)gm * DIMC + cc) =
                    make_float2(acc[mi][ni][0], acc[mi][ni][1]);
                *(float2*)(Cout + (size_t)(gm + 8) * DIMC + cc) =
                    make_float2(acc[mi][ni][2], acc[mi][ni][3]);
            }
    }
}

// ---------------------------------------------------------------------------
// Flash-style attention — VERBATIM Round-1 version (known good).
// ---------------------------------------------------------------------------
__global__ __launch_bounds__(256, 1)
void attn_k(const float* __restrict__ logd, const int* __restrict__ pW)
{
    __shared__ float Qs[HDD][66];
    __shared__ float Ks[HDD][36];
    __shared__ float Vs[32][HDD];
    __shared__ float Ss[64][33];
    __shared__ float m_s[64], l_s[64], al_s[64];
    __shared__ float kr_s[32], kc_s[32];
    __shared__ float decay_sh;

    const int bh = blockIdx.y;
    const int b = bh >> 3, h = bh & 7;
    const int q0 = blockIdx.x << 6;
    const int tid = threadIdx.x;
    const int Wg = pW ? *pW : 32;

    const size_t base = (size_t)(b * NHD + h) * NN * HDD;
    const float* qb = g_q + base;
    const float* kb = g_k + base;
    const float* vb = g_v + base;

    for (int i = tid; i < 64 * HDD; i += 256) {
        int m = i >> 6, d = i & 63;
        Qs[d][m] = qb[(size_t)(q0 + m) * HDD + d];
    }
    if (tid < 64) { m_s[tid] = -1e30f; l_s[tid] = 0.f; }
    if (tid == 0) decay_sh = log1pf(expf(logd[h]));   // softplus
    __syncthreads();

    const float decay = decay_sh;
    const int ty = tid >> 3;
    const int tx = tid & 7;
    const int r0 = ty << 1, r1 = r0 + 1;
    const float qr0 = (float)((q0 + r0) / Wg), qc0 = (float)((q0 + r0) % Wg);
    const float qr1 = (float)((q0 + r1) / Wg), qc1 = (float)((q0 + r1) % Wg);

    float acc0[8], acc1[8];
#pragma unroll
    for (int d = 0; d < 8; d++) { acc0[d] = 0.f; acc1[d] = 0.f; }
    const float scale = 0.125f;

    for (int t = 0; t < NN / 32; t++) {
        const int k0 = t << 5;
        for (int i = tid; i < 32 * HDD; i += 256) {
            int j = i >> 6, d = i & 63;
            Ks[d][j] = kb[(size_t)(k0 + j) * HDD + d];
            Vs[j][d] = vb[(size_t)(k0 + j) * HDD + d];
        }
        if (tid < 32) {
            kr_s[tid] = (float)((k0 + tid) / Wg);
            kc_s[tid] = (float)((k0 + tid) % Wg);
        }
        __syncthreads();

        // ---- S = Q K^T ----
        float s0[4] = {0.f, 0.f, 0.f, 0.f};
        float s1[4] = {0.f, 0.f, 0.f, 0.f};
#pragma unroll 16
        for (int d = 0; d < HDD; d++) {
            float a0 = Qs[d][r0];
            float a1 = Qs[d][r1];
            float4 bv = *(const float4*)(&Ks[d][tx << 2]);
            s0[0] = fmaf(a0, bv.x, s0[0]); s0[1] = fmaf(a0, bv.y, s0[1]);
            s0[2] = fmaf(a0, bv.z, s0[2]); s0[3] = fmaf(a0, bv.w, s0[3]);
            s1[0] = fmaf(a1, bv.x, s1[0]); s1[1] = fmaf(a1, bv.y, s1[1]);
            s1[2] = fmaf(a1, bv.z, s1[2]); s1[3] = fmaf(a1, bv.w, s1[3]);
        }
#pragma unroll
        for (int j = 0; j < 4; j++) {
            int kj = (tx << 2) + j;
            float d0 = fabsf(qr0 - kr_s[kj]) + fabsf(qc0 - kc_s[kj]);
            float d1 = fabsf(qr1 - kr_s[kj]) + fabsf(qc1 - kc_s[kj]);
            Ss[r0][kj] = fmaf(s0[j], scale, -decay * d0);
            Ss[r1][kj] = fmaf(s1[j], scale, -decay * d1);
        }
        __syncthreads();

        // ---- online softmax stats (1 thread per query row) ----
        if (tid < 64) {
            float mo = m_s[tid];
            float mx = mo;
#pragma unroll
            for (int j = 0; j < 32; j++) mx = fmaxf(mx, Ss[tid][j]);
            float alpha = __expf(mo - mx);
            float l = l_s[tid] * alpha;
#pragma unroll
            for (int j = 0; j < 32; j++) {
                float p = __expf(Ss[tid][j] - mx);
                Ss[tid][j] = p;
                l += p;
            }
            m_s[tid] = mx; l_s[tid] = l; al_s[tid] = alpha;
        }
        __syncthreads();

        // ---- rescale + O += P V ----
        const float al0 = al_s[r0], al1 = al_s[r1];
#pragma unroll
        for (int d = 0; d < 8; d++) { acc0[d] *= al0; acc1[d] *= al1; }
#pragma unroll 8
        for (int j = 0; j < 32; j++) {
            float p0 = Ss[r0][j], p1 = Ss[r1][j];
            float4 va = *(const float4*)(&Vs[j][tx << 3]);
            float4 vb4 = *(const float4*)(&Vs[j][(tx << 3) + 4]);
            acc0[0] = fmaf(p0, va.x,  acc0[0]); acc0[1] = fmaf(p0, va.y,  acc0[1]);
            acc0[2] = fmaf(p0, va.z,  acc0[2]); acc0[3] = fmaf(p0, va.w,  acc0[3]);
            acc0[4] = fmaf(p0, vb4.x, acc0[4]); acc0[5] = fmaf(p0, vb4.y, acc0[5]);
            acc0[6] = fmaf(p0, vb4.z, acc0[6]); acc0[7] = fmaf(p0, vb4.w, acc0[7]);
            acc1[0] = fmaf(p1, va.x,  acc1[0]); acc1[1] = fmaf(p1, va.y,  acc1[1]);
            acc1[2] = fmaf(p1, va.z,  acc1[2]); acc1[3] = fmaf(p1, va.w,  acc1[3]);
            acc1[4] = fmaf(p1, vb4.x, acc1[4]); acc1[5] = fmaf(p1, vb4.y, acc1[5]);
            acc1[6] = fmaf(p1, vb4.z, acc1[6]); acc1[7] = fmaf(p1, vb4.w, acc1[7]);
        }
        __syncthreads();
    }

    const float inv0 = 1.f / l_s[r0];
    const float inv1 = 1.f / l_s[r1];
    float* o0 = g_o + (size_t)(b * NN + q0 + r0) * DIMC + h * HDD + (tx << 3);
    float* o1 = g_o + (size_t)(b * NN + q0 + r1) * DIMC + h * HDD + (tx << 3);
    *(float4*)(o0)     = make_float4(acc0[0]*inv0, acc0[1]*inv0, acc0[2]*inv0, acc0[3]*inv0);
    *(float4*)(o0 + 4) = make_float4(acc0[4]*inv0, acc0[5]*inv0, acc0[6]*inv0, acc0[7]*inv0);
    *(float4*)(o1)     = make_float4(acc1[0]*inv1, acc1[1]*inv1, acc1[2]*inv1, acc1[3]*inv1);
    *(float4*)(o1 + 4) = make_float4(acc1[4]*inv1, acc1[5]*inv1, acc1[6]*inv1, acc1[7]*inv1);
}

// ---------------------------------------------------------------------------
extern "C" void kernel_launch(void* const* d_in, const int* in_sizes, int n_in,
                              void* d_out, int out_size)
{
    const float* x      = (const float*)d_in[0];
    const float* w_qkv  = (const float*)d_in[1];
    const float* w_proj = (const float*)d_in[2];
    const float* logd   = (const float*)d_in[3];
    const int*   pW     = (n_in > 5) ? (const int*)d_in[5] : nullptr;
    float* out = (float*)d_out;

    // fp32 -> bf16 hi/lo splits (destinations bound in device code)
    cvt_k<0><<<(MTOT * DIMC / 4 + 255) / 256, 256>>>(x, MTOT * DIMC);
    cvt_k<1><<<(3 * DIMC * DIMC / 4 + 255) / 256, 256>>>(w_qkv, 3 * DIMC * DIMC);
    cvt_k<2><<<(DIMC * DIMC / 4 + 255) / 256, 256>>>(w_proj, DIMC * DIMC);

    // qkv projection on HMMA -> g_q/g_k/g_v (fp32)
    hgemm_k<0><<<dim3(24, 64), 256>>>(nullptr);

    // spatial-decay flash attention (round-1 exact) -> g_o (fp32)
    attn_k<<<dim3(16, 64), 256>>>(logd, pW);

    // attn out -> bf16 hi/lo (src = g_o bound in device code), then proj
    cvt_k<3><<<(MTOT * DIMC / 4 + 255) / 256, 256>>>(nullptr, MTOT * DIMC);
    hgemm_k<1><<<dim3(8, 64), 256>>>(out);
}

// round 7
// speedup vs baseline: 2.5846x; 2.2281x over previous
#include <cuda_runtime.h>
#include <cuda_bf16.h>
#include <cstdint>
#include <math.h>

#define DIMC 512
#define NHD  8
#define HDD  64
#define BB   8
#define NN   1024
#define MTOT (BB*NN)   // 8192
#define QKV  (BB*NHD*NN*HDD)

// ---------------- scratch (allocation-free) ----------------
__device__ __nv_bfloat16 gx_hi[MTOT*DIMC],  gx_lo[MTOT*DIMC];
__device__ __nv_bfloat16 gwq_hi[3*DIMC*DIMC], gwq_lo[3*DIMC*DIMC];
__device__ __nv_bfloat16 gwp_hi[DIMC*DIMC],  gwp_lo[DIMC*DIMC];
__device__ __nv_bfloat16 gq_hi[QKV],  gq_lo[QKV];    // [bh][n][d]
__device__ __nv_bfloat16 gk_hi[QKV],  gk_lo[QKV];    // [bh][n][d]
__device__ __nv_bfloat16 gvt_hi[QKV], gvt_lo[QKV];   // [bh][d][n]  (transposed!)
__device__ __nv_bfloat16 go_hi[MTOT*DIMC], go_lo[MTOT*DIMC];

// ---------------- fp32 -> bf16 hi/lo split ----------------
// Destinations bound in DEVICE code (never pass __device__ symbols from host).
template<int DST>
__global__ void cvt_k(const float* __restrict__ s, int n)
{
    __nv_bfloat16* hi;
    __nv_bfloat16* lo;
    if (DST == 0)      { hi = gx_hi;  lo = gx_lo;  }
    else if (DST == 1) { hi = gwq_hi; lo = gwq_lo; }
    else               { hi = gwp_hi; lo = gwp_lo; }

    int i = (blockIdx.x * blockDim.x + threadIdx.x) * 4;
    if (i >= n) return;
    float4 v = *(const float4*)(s + i);
    __nv_bfloat16 h0 = __float2bfloat16(v.x);
    __nv_bfloat16 h1 = __float2bfloat16(v.y);
    __nv_bfloat16 h2 = __float2bfloat16(v.z);
    __nv_bfloat16 h3 = __float2bfloat16(v.w);
    __nv_bfloat162 hp0; hp0.x = h0; hp0.y = h1;
    __nv_bfloat162 hp1; hp1.x = h2; hp1.y = h3;
    __nv_bfloat162 lp0;
    lp0.x = __float2bfloat16(v.x - __bfloat162float(h0));
    lp0.y = __float2bfloat16(v.y - __bfloat162float(h1));
    __nv_bfloat162 lp1;
    lp1.x = __float2bfloat16(v.z - __bfloat162float(h2));
    lp1.y = __float2bfloat16(v.w - __bfloat162float(h3));
    *(__nv_bfloat162*)(hi + i)     = hp0;
    *(__nv_bfloat162*)(hi + i + 2) = hp1;
    *(__nv_bfloat162*)(lo + i)     = lp0;
    *(__nv_bfloat162*)(lo + i + 2) = lp1;
}

// ---------------- mma.sync m16n8k16 bf16 helper ----------------
__device__ __forceinline__ void mma4(float* c, const uint32_t* a,
                                     uint32_t b0, uint32_t b1)
{
    asm volatile(
        "mma.sync.aligned.m16n8k16.row.col.f32.bf16.bf16.f32 "
        "{%0,%1,%2,%3}, {%4,%5,%6,%7}, {%8,%9}, {%0,%1,%2,%3};"
        : "+f"(c[0]), "+f"(c[1]), "+f"(c[2]), "+f"(c[3])
        : "r"(a[0]), "r"(a[1]), "r"(a[2]), "r"(a[3]), "r"(b0), "r"(b1));
}

__device__ __forceinline__ void split2(float v0, float v1,
                                       uint32_t& hi, uint32_t& lo)
{
    __nv_bfloat16 hx = __float2bfloat16(v0);
    __nv_bfloat16 hy = __float2bfloat16(v1);
    __nv_bfloat162 hp; hp.x = hx; hp.y = hy;
    hi = *(uint32_t*)&hp;
    __nv_bfloat162 lp;
    lp.x = __float2bfloat16(v0 - __bfloat162float(hx));
    lp.y = __float2bfloat16(v1 - __bfloat162float(hy));
    lo = *(uint32_t*)&lp;
}

// ---------------------------------------------------------------------------
// HMMA GEMM (validated R6 mainloop). MODE 0: qkv projection, epilogue writes
// bf16 hi/lo directly: q,k at [bh][n][d]; v TRANSPOSED at [bh][d][n].
// MODE 1: proj, fp32 into d_out.
// ---------------------------------------------------------------------------
#define LDA_S 40

template<int MODE>
__global__ __launch_bounds__(256, 2)
void hgemm_k(float* __restrict__ Cout)
{
    __shared__ __align__(16) __nv_bfloat16 As[128 * LDA_S];
    __shared__ __align__(16) __nv_bfloat16 Bs[64 * LDA_S];

    const int tid = threadIdx.x;
    const int wid = tid >> 5, lane = tid & 31;
    const int g = lane >> 2, t = lane & 3;
    const int m0 = blockIdx.y << 7;
    const int n0 = blockIdx.x << 6;
    const int wm = (wid & 3) << 5;
    const int wn = (wid >> 2) << 5;

    const __nv_bfloat16* a_hi = (MODE == 0) ? gx_hi : go_hi;
    const __nv_bfloat16* a_lo = (MODE == 0) ? gx_lo : go_lo;
    const __nv_bfloat16* b_hi = (MODE == 0) ? gwq_hi : gwp_hi;
    const __nv_bfloat16* b_lo = (MODE == 0) ? gwq_lo : gwp_lo;

    float acc[2][4][4];
#pragma unroll
    for (int mi = 0; mi < 2; mi++)
#pragma unroll
        for (int ni = 0; ni < 4; ni++)
#pragma unroll
            for (int c = 0; c < 4; c++) acc[mi][ni][c] = 0.f;

    for (int chunk = 0; chunk < 48; chunk++) {
        const int pass = chunk >> 4;
        const int kc = (chunk & 15) << 5;
        const __nv_bfloat16* asrc = (pass == 1) ? a_lo : a_hi;
        const __nv_bfloat16* bsrc = (pass == 2) ? b_lo : b_hi;

        __syncthreads();
#pragma unroll
        for (int it = 0; it < 2; it++) {
            int idx = tid + (it << 8);
            int row = idx >> 2, cu = idx & 3;
            uint4 v = *(const uint4*)(asrc + (size_t)(m0 + row) * DIMC + kc + cu * 8);
            *(uint4*)(As + row * LDA_S + cu * 8) = v;
        }
        {
            int row = tid >> 2, cu = tid & 3;
            uint4 v = *(const uint4*)(bsrc + (size_t)(n0 + row) * DIMC + kc + cu * 8);
            *(uint4*)(Bs + row * LDA_S + cu * 8) = v;
        }
        __syncthreads();

#pragma unroll
        for (int ks = 0; ks < 2; ks++) {
            const int k0 = ks << 4;
            uint32_t af[2][4];
#pragma unroll
            for (int mi = 0; mi < 2; mi++) {
                const __nv_bfloat16* ab = As + (wm + (mi << 4)) * LDA_S + k0;
                af[mi][0] = *(const uint32_t*)(ab + g * LDA_S + 2 * t);
                af[mi][1] = *(const uint32_t*)(ab + (g + 8) * LDA_S + 2 * t);
                af[mi][2] = *(const uint32_t*)(ab + g * LDA_S + 2 * t + 8);
                af[mi][3] = *(const uint32_t*)(ab + (g + 8) * LDA_S + 2 * t + 8);
            }
#pragma unroll
            for (int ni = 0; ni < 4; ni++) {
                const __nv_bfloat16* bb = Bs + (wn + (ni << 3) + g) * LDA_S + k0;
                uint32_t b0 = *(const uint32_t*)(bb + 2 * t);
                uint32_t b1 = *(const uint32_t*)(bb + 2 * t + 8);
#pragma unroll
                for (int mi = 0; mi < 2; mi++)
                    mma4(acc[mi][ni], af[mi], b0, b1);
            }
        }
    }

    // -------- epilogue --------
    if (MODE == 0) {
        const int which = n0 >> 9;            // 0=q 1=k 2=v
        const int h = (n0 >> 6) & (NHD - 1);
#pragma unroll
        for (int mi = 0; mi < 2; mi++)
#pragma unroll
            for (int ni = 0; ni < 4; ni++) {
                int gm  = m0 + wm + (mi << 4) + g;
                int gm2 = gm + 8;
                int d = wn + (ni << 3) + 2 * t;
                int b1_ = gm >> 10,  n1_ = gm & (NN - 1);
                int b2_ = gm2 >> 10, n2_ = gm2 & (NN - 1);
                uint32_t hiA, loA, hiB, loB;
                split2(acc[mi][ni][0], acc[mi][ni][1], hiA, loA);
                split2(acc[mi][ni][2], acc[mi][ni][3], hiB, loB);
                if (which == 2) {
                    // transposed: element (d, n)
                    __nv_bfloat162 hA = *(__nv_bfloat162*)&hiA;
                    __nv_bfloat162 lA = *(__nv_bfloat162*)&loA;
                    __nv_bfloat162 hB = *(__nv_bfloat162*)&hiB;
                    __nv_bfloat162 lB = *(__nv_bfloat162*)&loB;
                    size_t vb1 = ((size_t)((b1_ * NHD + h) * HDD + d)) * NN + n1_;
                    gvt_hi[vb1]      = hA.x; gvt_lo[vb1]      = lA.x;
                    gvt_hi[vb1 + NN] = hA.y; gvt_lo[vb1 + NN] = lA.y;
                    size_t vb2 = ((size_t)((b2_ * NHD + h) * HDD + d)) * NN + n2_;
                    gvt_hi[vb2]      = hB.x; gvt_lo[vb2]      = lB.x;
                    gvt_hi[vb2 + NN] = hB.y; gvt_lo[vb2 + NN] = lB.y;
                } else {
                    __nv_bfloat16* dh = which ? gk_hi : gq_hi;
                    __nv_bfloat16* dl = which ? gk_lo : gq_lo;
                    size_t qb1 = ((size_t)((b1_ * NHD + h) * NN + n1_)) * HDD + d;
                    *(uint32_t*)(dh + qb1) = hiA;
                    *(uint32_t*)(dl + qb1) = loA;
                    size_t qb2 = ((size_t)((b2_ * NHD + h) * NN + n2_)) * HDD + d;
                    *(uint32_t*)(dh + qb2) = hiB;
                    *(uint32_t*)(dl + qb2) = loB;
                }
            }
    } else {
#pragma unroll
        for (int mi = 0; mi < 2; mi++)
#pragma unroll
            for (int ni = 0; ni < 4; ni++) {
                int gm = m0 + wm + (mi << 4) + g;
                int cc = n0 + wn + (ni << 3) + 2 * t;
                *(float2*)(Cout + (size_t)gm * DIMC + cc) =
                    make_float2(acc[mi][ni][0], acc[mi][ni][1]);
                *(float2*)(Cout + (size_t)(gm + 8) * DIMC + cc) =
                    make_float2(acc[mi][ni][2], acc[mi][ni][3]);
            }
    }
}

// ---------------------------------------------------------------------------
// Tensor-core flash attention.
// Block = (b,h) x 128-query tile, 8 warps; warp owns 16 query rows.
// K tiles of 64 keys. S = QhKh + QlKh + QhKl; O += PhVh + PlVh + PhVl.
// Softmax per-row fully within one warp (quad shuffles).
// ---------------------------------------------------------------------------
#define KPAD 72   // smem row stride (64 data + 8) -> conflict-free frag reads

__global__ __launch_bounds__(256, 1)
void attn_k(const float* __restrict__ logd, const int* __restrict__ pW)
{
    __shared__ __align__(16) __nv_bfloat16 Ksh[64 * KPAD];
    __shared__ __align__(16) __nv_bfloat16 Ksl[64 * KPAD];
    __shared__ __align__(16) __nv_bfloat16 Vsh[64 * KPAD];
    __shared__ __align__(16) __nv_bfloat16 Vsl[64 * KPAD];

    const int bh = blockIdx.y;
    const int b = bh >> 3, h = bh & 7;
    const int q0 = blockIdx.x << 7;
    const int tid = threadIdx.x;
    const int wid = tid >> 5, lane = tid & 31;
    const int g = lane >> 2, t = lane & 3;

    const int Wg = pW ? *pW : 32;
    const float invW = 1.0f / (float)Wg;
    const float decay = log1pf(expf(logd[h]));   // softplus
    const float scale = 0.125f;

    const size_t kbase  = (size_t)bh * NN * HDD;

    // ---- preload Q fragments (hi/lo) straight from gmem ----
    const int qrow0 = q0 + (wid << 4) + g;
    const int qrow1 = qrow0 + 8;
    uint32_t qh[4][4], ql[4][4];
#pragma unroll
    for (int kc = 0; kc < 4; kc++) {
        int c0 = kc * 16 + 2 * t;
        qh[kc][0] = *(const uint32_t*)(gq_hi + kbase + (size_t)qrow0 * HDD + c0);
        qh[kc][1] = *(const uint32_t*)(gq_hi + kbase + (size_t)qrow1 * HDD + c0);
        qh[kc][2] = *(const uint32_t*)(gq_hi + kbase + (size_t)qrow0 * HDD + c0 + 8);
        qh[kc][3] = *(const uint32_t*)(gq_hi + kbase + (size_t)qrow1 * HDD + c0 + 8);
        ql[kc][0] = *(const uint32_t*)(gq_lo + kbase + (size_t)qrow0 * HDD + c0);
        ql[kc][1] = *(const uint32_t*)(gq_lo + kbase + (size_t)qrow1 * HDD + c0);
        ql[kc][2] = *(const uint32_t*)(gq_lo + kbase + (size_t)qrow0 * HDD + c0 + 8);
        ql[kc][3] = *(const uint32_t*)(gq_lo + kbase + (size_t)qrow1 * HDD + c0 + 8);
    }

    // query grid coords
    int qri0 = (int)(((float)qrow0 + 0.5f) * invW);
    int qri1 = (int)(((float)qrow1 + 0.5f) * invW);
    const float qr0 = (float)qri0, qc0 = (float)(qrow0 - qri0 * Wg);
    const float qr1 = (float)qri1, qc1 = (float)(qrow1 - qri1 * Wg);

    float mg0 = -1e30f, lg0 = 0.f, mg1 = -1e30f, lg1 = 0.f;
    float accO[8][4];
#pragma unroll
    for (int ni = 0; ni < 8; ni++)
#pragma unroll
        for (int c = 0; c < 4; c++) accO[ni][c] = 0.f;

    for (int tk = 0; tk < 16; tk++) {
        const int k0 = tk << 6;
        // ---- stage K (hi/lo) and Vt (hi/lo) ----
#pragma unroll
        for (int i = 0; i < 2; i++) {
            int idx = tid + (i << 8);
            int row = idx >> 3, cu = (idx & 7) << 3;
            *(uint4*)(Ksh + row * KPAD + cu) =
                *(const uint4*)(gk_hi + kbase + (size_t)(k0 + row) * HDD + cu);
            *(uint4*)(Ksl + row * KPAD + cu) =
                *(const uint4*)(gk_lo + kbase + (size_t)(k0 + row) * HDD + cu);
            *(uint4*)(Vsh + row * KPAD + cu) =
                *(const uint4*)(gvt_hi + kbase + (size_t)row * NN + k0 + cu);
            *(uint4*)(Vsl + row * KPAD + cu) =
                *(const uint4*)(gvt_lo + kbase + (size_t)row * NN + k0 + cu);
        }
        __syncthreads();

        // ---- S = Q K^T (3 passes) ----
        float S[8][4];
#pragma unroll
        for (int ni = 0; ni < 8; ni++)
#pragma unroll
            for (int c = 0; c < 4; c++) S[ni][c] = 0.f;

#pragma unroll
        for (int kc = 0; kc < 4; kc++) {
#pragma unroll
            for (int ni = 0; ni < 8; ni++) {
                const __nv_bfloat16* kh = Ksh + (ni * 8 + g) * KPAD + kc * 16 + 2 * t;
                uint32_t b0 = *(const uint32_t*)kh;
                uint32_t b1 = *(const uint32_t*)(kh + 8);
                mma4(S[ni], qh[kc], b0, b1);
                mma4(S[ni], ql[kc], b0, b1);
                const __nv_bfloat16* kl = Ksl + (ni * 8 + g) * KPAD + kc * 16 + 2 * t;
                uint32_t c0 = *(const uint32_t*)kl;
                uint32_t c1 = *(const uint32_t*)(kl + 8);
                mma4(S[ni], qh[kc], c0, c1);
            }
        }

        // ---- bias ----
#pragma unroll
        for (int ni = 0; ni < 8; ni++) {
            int kA = k0 + ni * 8 + 2 * t;
            int kB = kA + 1;
            int krAi = (int)(((float)kA + 0.5f) * invW);
            int krBi = (int)(((float)kB + 0.5f) * invW);
            float krA = (float)krAi, kcA = (float)(kA - krAi * Wg);
            float krB = (float)krBi, kcB = (float)(kB - krBi * Wg);
            float dA0 = fabsf(qr0 - krA) + fabsf(qc0 - kcA);
            float dB0 = fabsf(qr0 - krB) + fabsf(qc0 - kcB);
            float dA1 = fabsf(qr1 - krA) + fabsf(qc1 - kcA);
            float dB1 = fabsf(qr1 - krB) + fabsf(qc1 - kcB);
            S[ni][0] = fmaf(S[ni][0], scale, -decay * dA0);
            S[ni][1] = fmaf(S[ni][1], scale, -decay * dB0);
            S[ni][2] = fmaf(S[ni][2], scale, -decay * dA1);
            S[ni][3] = fmaf(S[ni][3], scale, -decay * dB1);
        }

        // ---- online softmax (rows g / g+8, reduced over quad lanes) ----
        float mx0 = -1e30f, mx1 = -1e30f;
#pragma unroll
        for (int ni = 0; ni < 8; ni++) {
            mx0 = fmaxf(mx0, fmaxf(S[ni][0], S[ni][1]));
            mx1 = fmaxf(mx1, fmaxf(S[ni][2], S[ni][3]));
        }
        mx0 = fmaxf(mx0, __shfl_xor_sync(0xffffffffu, mx0, 1));
        mx0 = fmaxf(mx0, __shfl_xor_sync(0xffffffffu, mx0, 2));
        mx1 = fmaxf(mx1, __shfl_xor_sync(0xffffffffu, mx1, 1));
        mx1 = fmaxf(mx1, __shfl_xor_sync(0xffffffffu, mx1, 2));
        float nm0 = fmaxf(mg0, mx0), nm1 = fmaxf(mg1, mx1);
        float al0 = __expf(mg0 - nm0), al1 = __expf(mg1 - nm1);
        float sum0 = 0.f, sum1 = 0.f;
#pragma unroll
        for (int ni = 0; ni < 8; ni++) {
            S[ni][0] = __expf(S[ni][0] - nm0); sum0 += S[ni][0];
            S[ni][1] = __expf(S[ni][1] - nm0); sum0 += S[ni][1];
            S[ni][2] = __expf(S[ni][2] - nm1); sum1 += S[ni][2];
            S[ni][3] = __expf(S[ni][3] - nm1); sum1 += S[ni][3];
        }
        sum0 += __shfl_xor_sync(0xffffffffu, sum0, 1);
        sum0 += __shfl_xor_sync(0xffffffffu, sum0, 2);
        sum1 += __shfl_xor_sync(0xffffffffu, sum1, 1);
        sum1 += __shfl_xor_sync(0xffffffffu, sum1, 2);
        lg0 = lg0 * al0 + sum0;  mg0 = nm0;
        lg1 = lg1 * al1 + sum1;  mg1 = nm1;
#pragma unroll
        for (int ni = 0; ni < 8; ni++) {
            accO[ni][0] *= al0; accO[ni][1] *= al0;
            accO[ni][2] *= al1; accO[ni][3] *= al1;
        }

        // ---- O += P V (P packed from C-frags to A-frags in registers) ----
#pragma unroll
        for (int kc = 0; kc < 4; kc++) {
            const int nA = 2 * kc, nB = 2 * kc + 1;
            uint32_t ph[4], pl[4];
            split2(S[nA][0], S[nA][1], ph[0], pl[0]);
            split2(S[nA][2], S[nA][3], ph[1], pl[1]);
            split2(S[nB][0], S[nB][1], ph[2], pl[2]);
            split2(S[nB][2], S[nB][3], ph[3], pl[3]);
#pragma unroll
            for (int ni = 0; ni < 8; ni++) {
                const __nv_bfloat16* vh = Vsh + (ni * 8 + g) * KPAD + kc * 16 + 2 * t;
                uint32_t b0 = *(const uint32_t*)vh;
                uint32_t b1 = *(const uint32_t*)(vh + 8);
                mma4(accO[ni], ph, b0, b1);
                mma4(accO[ni], pl, b0, b1);
                const __nv_bfloat16* vl = Vsl + (ni * 8 + g) * KPAD + kc * 16 + 2 * t;
                uint32_t c0 = *(const uint32_t*)vl;
                uint32_t c1 = *(const uint32_t*)(vl + 8);
                mma4(accO[ni], ph, c0, c1);
            }
        }
        __syncthreads();
    }

    // ---- epilogue: O/l -> go_hi/go_lo at [b][n][h*64+d] ----
    const float inv0 = 1.f / lg0;
    const float inv1 = 1.f / lg1;
#pragma unroll
    for (int ni = 0; ni < 8; ni++) {
        int d = ni * 8 + 2 * t;
        uint32_t hiA, loA, hiB, loB;
        split2(accO[ni][0] * inv0, accO[ni][1] * inv0, hiA, loA);
        split2(accO[ni][2] * inv1, accO[ni][3] * inv1, hiB, loB);
        size_t o0 = ((size_t)(b * NN + qrow0)) * DIMC + h * HDD + d;
        size_t o1 = ((size_t)(b * NN + qrow1)) * DIMC + h * HDD + d;
        *(uint32_t*)(go_hi + o0) = hiA;
        *(uint32_t*)(go_lo + o0) = loA;
        *(uint32_t*)(go_hi + o1) = hiB;
        *(uint32_t*)(go_lo + o1) = loB;
    }
}

// ---------------------------------------------------------------------------
extern "C" void kernel_launch(void* const* d_in, const int* in_sizes, int n_in,
                              void* d_out, int out_size)
{
    const float* x      = (const float*)d_in[0];
    const float* w_qkv  = (const float*)d_in[1];
    const float* w_proj = (const float*)d_in[2];
    const float* logd   = (const float*)d_in[3];
    const int*   pW     = (n_in > 5) ? (const int*)d_in[5] : nullptr;
    float* out = (float*)d_out;

    // fp32 -> bf16 hi/lo splits
    cvt_k<0><<<(MTOT * DIMC / 4 + 255) / 256, 256>>>(x, MTOT * DIMC);
    cvt_k<1><<<(3 * DIMC * DIMC / 4 + 255) / 256, 256>>>(w_qkv, 3 * DIMC * DIMC);
    cvt_k<2><<<(DIMC * DIMC / 4 + 255) / 256, 256>>>(w_proj, DIMC * DIMC);

    // qkv projection -> gq/gk (bf16 hi/lo) + gvt (transposed bf16 hi/lo)
    hgemm_k<0><<<dim3(24, 64), 256>>>(nullptr);

    // tensor-core flash attention -> go_hi/go_lo
    attn_k<<<dim3(8, 64), 256>>>(logd, pW);

    // output projection -> d_out
    hgemm_k<1><<<dim3(8, 64), 256>>>(out);
}

// round 8
// speedup vs baseline: 2.7765x; 1.0742x over previous
#include <cuda_runtime.h>
#include <cuda_bf16.h>
#include <cstdint>
#include <math.h>

#define DIMC 512
#define NHD  8
#define HDD  64
#define BB   8
#define NN   1024
#define MTOT (BB*NN)   // 8192
#define QKV  (BB*NHD*NN*HDD)

// ---------------- scratch (allocation-free) ----------------
__device__ __align__(16) __nv_bfloat16 gx_hi[MTOT*DIMC],  gx_lo[MTOT*DIMC];
__device__ __align__(16) __nv_bfloat16 gwq_hi[3*DIMC*DIMC], gwq_lo[3*DIMC*DIMC];
__device__ __align__(16) __nv_bfloat16 gwp_hi[DIMC*DIMC],  gwp_lo[DIMC*DIMC];
__device__ __align__(16) __nv_bfloat16 gq_hi[QKV],  gq_lo[QKV];    // [bh][n][d]
__device__ __align__(16) __nv_bfloat16 gk_hi[QKV],  gk_lo[QKV];    // [bh][n][d]
__device__ __align__(16) __nv_bfloat16 gvt_hi[QKV], gvt_lo[QKV];   // [bh][d][n]
__device__ __align__(16) __nv_bfloat16 go_hi[MTOT*DIMC], go_lo[MTOT*DIMC];

// ---------------- fp32 -> bf16 hi/lo split ----------------
template<int DST>
__global__ void cvt_k(const float* __restrict__ s, int n)
{
    __nv_bfloat16* hi;
    __nv_bfloat16* lo;
    if (DST == 0)      { hi = gx_hi;  lo = gx_lo;  }
    else if (DST == 1) { hi = gwq_hi; lo = gwq_lo; }
    else               { hi = gwp_hi; lo = gwp_lo; }

    int i = (blockIdx.x * blockDim.x + threadIdx.x) * 4;
    if (i >= n) return;
    float4 v = *(const float4*)(s + i);
    __nv_bfloat16 h0 = __float2bfloat16(v.x);
    __nv_bfloat16 h1 = __float2bfloat16(v.y);
    __nv_bfloat16 h2 = __float2bfloat16(v.z);
    __nv_bfloat16 h3 = __float2bfloat16(v.w);
    __nv_bfloat162 hp0; hp0.x = h0; hp0.y = h1;
    __nv_bfloat162 hp1; hp1.x = h2; hp1.y = h3;
    __nv_bfloat162 lp0;
    lp0.x = __float2bfloat16(v.x - __bfloat162float(h0));
    lp0.y = __float2bfloat16(v.y - __bfloat162float(h1));
    __nv_bfloat162 lp1;
    lp1.x = __float2bfloat16(v.z - __bfloat162float(h2));
    lp1.y = __float2bfloat16(v.w - __bfloat162float(h3));
    *(__nv_bfloat162*)(hi + i)     = hp0;
    *(__nv_bfloat162*)(hi + i + 2) = hp1;
    *(__nv_bfloat162*)(lo + i)     = lp0;
    *(__nv_bfloat162*)(lo + i + 2) = lp1;
}

// ---------------- helpers ----------------
__device__ __forceinline__ void mma4(float* c, const uint32_t* a,
                                     uint32_t b0, uint32_t b1)
{
    asm volatile(
        "mma.sync.aligned.m16n8k16.row.col.f32.bf16.bf16.f32 "
        "{%0,%1,%2,%3}, {%4,%5,%6,%7}, {%8,%9}, {%0,%1,%2,%3};"
        : "+f"(c[0]), "+f"(c[1]), "+f"(c[2]), "+f"(c[3])
        : "r"(a[0]), "r"(a[1]), "r"(a[2]), "r"(a[3]), "r"(b0), "r"(b1));
}

__device__ __forceinline__ void split2(float v0, float v1,
                                       uint32_t& hi, uint32_t& lo)
{
    __nv_bfloat16 hx = __float2bfloat16(v0);
    __nv_bfloat16 hy = __float2bfloat16(v1);
    __nv_bfloat162 hp; hp.x = hx; hp.y = hy;
    hi = *(uint32_t*)&hp;
    __nv_bfloat162 lp;
    lp.x = __float2bfloat16(v0 - __bfloat162float(hx));
    lp.y = __float2bfloat16(v1 - __bfloat162float(hy));
    lo = *(uint32_t*)&lp;
}

__device__ __forceinline__ void cpa16(void* smem, const void* gmem)
{
    uint32_t s = (uint32_t)__cvta_generic_to_shared(smem);
    asm volatile("cp.async.ca.shared.global [%0], [%1], 16;"
                 :: "r"(s), "l"(gmem));
}
__device__ __forceinline__ void cpa_commit()
{ asm volatile("cp.async.commit_group;" ::: "memory"); }
template<int N>
__device__ __forceinline__ void cpa_wait()
{ asm volatile("cp.async.wait_group %0;" :: "n"(N) : "memory"); }

// ---------------------------------------------------------------------------
// HMMA GEMM, 3-stage cp.async pipeline.
// C[M,NC] = A[M,512] @ W[NC,512]^T, split-bf16: Ah Bh + Al Bh + Ah Bl.
// Block tile 128x64, 8 warps (4m x 2n), warp tile 32x32, K-chunk 32.
// ---------------------------------------------------------------------------
#define LDA_S 40
#define NCHUNK 48

template<int MODE>
__global__ __launch_bounds__(256, 2)
void hgemm_k(float* __restrict__ Cout)
{
    __shared__ __align__(16) __nv_bfloat16 As[3][128 * LDA_S];
    __shared__ __align__(16) __nv_bfloat16 Bs[3][64 * LDA_S];

    const int tid = threadIdx.x;
    const int wid = tid >> 5, lane = tid & 31;
    const int g = lane >> 2, t = lane & 3;
    const int m0 = blockIdx.y << 7;
    const int n0 = blockIdx.x << 6;
    const int wm = (wid & 3) << 5;
    const int wn = (wid >> 2) << 5;

    const __nv_bfloat16* a_hi = (MODE == 0) ? gx_hi : go_hi;
    const __nv_bfloat16* a_lo = (MODE == 0) ? gx_lo : go_lo;
    const __nv_bfloat16* b_hi = (MODE == 0) ? gwq_hi : gwp_hi;
    const __nv_bfloat16* b_lo = (MODE == 0) ? gwq_lo : gwp_lo;

    // per-thread staging coords
    const int arow0 = tid >> 2,        acu = (tid & 3) << 3;        // +2 rows of 128
    const int brow  = tid >> 2,        bcu = (tid & 3) << 3;

    auto load_chunk = [&](int c, int s) {
        const int pass = c >> 4;
        const int kc = (c & 15) << 5;
        const __nv_bfloat16* asrc = (pass == 1) ? a_lo : a_hi;
        const __nv_bfloat16* bsrc = (pass == 2) ? b_lo : b_hi;
        cpa16(As[s] + arow0 * LDA_S + acu,
              asrc + (size_t)(m0 + arow0) * DIMC + kc + acu);
        cpa16(As[s] + (arow0 + 64) * LDA_S + acu,
              asrc + (size_t)(m0 + arow0 + 64) * DIMC + kc + acu);
        cpa16(Bs[s] + brow * LDA_S + bcu,
              bsrc + (size_t)(n0 + brow) * DIMC + kc + bcu);
        cpa_commit();
    };

    float acc[2][4][4];
#pragma unroll
    for (int mi = 0; mi < 2; mi++)
#pragma unroll
        for (int ni = 0; ni < 4; ni++)
#pragma unroll
            for (int c = 0; c < 4; c++) acc[mi][ni][c] = 0.f;

    load_chunk(0, 0);
    load_chunk(1, 1);

    for (int c = 0; c < NCHUNK; c++) {
        const int s = c % 3;
        if (c + 1 < NCHUNK) cpa_wait<1>(); else cpa_wait<0>();
        __syncthreads();
        if (c + 2 < NCHUNK) load_chunk(c + 2, (c + 2) % 3);

        const __nv_bfloat16* Ab = As[s];
        const __nv_bfloat16* Bb = Bs[s];
#pragma unroll
        for (int ks = 0; ks < 2; ks++) {
            const int k0 = ks << 4;
            uint32_t af[2][4];
#pragma unroll
            for (int mi = 0; mi < 2; mi++) {
                const __nv_bfloat16* ab = Ab + (wm + (mi << 4)) * LDA_S + k0;
                af[mi][0] = *(const uint32_t*)(ab + g * LDA_S + 2 * t);
                af[mi][1] = *(const uint32_t*)(ab + (g + 8) * LDA_S + 2 * t);
                af[mi][2] = *(const uint32_t*)(ab + g * LDA_S + 2 * t + 8);
                af[mi][3] = *(const uint32_t*)(ab + (g + 8) * LDA_S + 2 * t + 8);
            }
#pragma unroll
            for (int ni = 0; ni < 4; ni++) {
                const __nv_bfloat16* bb = Bb + (wn + (ni << 3) + g) * LDA_S + k0;
                uint32_t b0 = *(const uint32_t*)(bb + 2 * t);
                uint32_t b1 = *(const uint32_t*)(bb + 2 * t + 8);
#pragma unroll
                for (int mi = 0; mi < 2; mi++)
                    mma4(acc[mi][ni], af[mi], b0, b1);
            }
        }
    }

    // -------- epilogue (unchanged, validated) --------
    if (MODE == 0) {
        const int which = n0 >> 9;            // 0=q 1=k 2=v
        const int h = (n0 >> 6) & (NHD - 1);
#pragma unroll
        for (int mi = 0; mi < 2; mi++)
#pragma unroll
            for (int ni = 0; ni < 4; ni++) {
                int gm  = m0 + wm + (mi << 4) + g;
                int gm2 = gm + 8;
                int d = wn + (ni << 3) + 2 * t;
                int b1_ = gm >> 10,  n1_ = gm & (NN - 1);
                int b2_ = gm2 >> 10, n2_ = gm2 & (NN - 1);
                uint32_t hiA, loA, hiB, loB;
                split2(acc[mi][ni][0], acc[mi][ni][1], hiA, loA);
                split2(acc[mi][ni][2], acc[mi][ni][3], hiB, loB);
                if (which == 2) {
                    __nv_bfloat162 hA = *(__nv_bfloat162*)&hiA;
                    __nv_bfloat162 lA = *(__nv_bfloat162*)&loA;
                    __nv_bfloat162 hB = *(__nv_bfloat162*)&hiB;
                    __nv_bfloat162 lB = *(__nv_bfloat162*)&loB;
                    size_t vb1 = ((size_t)((b1_ * NHD + h) * HDD + d)) * NN + n1_;
                    gvt_hi[vb1]      = hA.x; gvt_lo[vb1]      = lA.x;
                    gvt_hi[vb1 + NN] = hA.y; gvt_lo[vb1 + NN] = lA.y;
                    size_t vb2 = ((size_t)((b2_ * NHD + h) * HDD + d)) * NN + n2_;
                    gvt_hi[vb2]      = hB.x; gvt_lo[vb2]      = lB.x;
                    gvt_hi[vb2 + NN] = hB.y; gvt_lo[vb2 + NN] = lB.y;
                } else {
                    __nv_bfloat16* dh = which ? gk_hi : gq_hi;
                    __nv_bfloat16* dl = which ? gk_lo : gq_lo;
                    size_t qb1 = ((size_t)((b1_ * NHD + h) * NN + n1_)) * HDD + d;
                    *(uint32_t*)(dh + qb1) = hiA;
                    *(uint32_t*)(dl + qb1) = loA;
                    size_t qb2 = ((size_t)((b2_ * NHD + h) * NN + n2_)) * HDD + d;
                    *(uint32_t*)(dh + qb2) = hiB;
                    *(uint32_t*)(dl + qb2) = loB;
                }
            }
    } else {
#pragma unroll
        for (int mi = 0; mi < 2; mi++)
#pragma unroll
            for (int ni = 0; ni < 4; ni++) {
                int gm = m0 + wm + (mi << 4) + g;
                int cc = n0 + wn + (ni << 3) + 2 * t;
                *(float2*)(Cout + (size_t)gm * DIMC + cc) =
                    make_float2(acc[mi][ni][0], acc[mi][ni][1]);
                *(float2*)(Cout + (size_t)(gm + 8) * DIMC + cc) =
                    make_float2(acc[mi][ni][2], acc[mi][ni][3]);
            }
    }
}

// ---------------------------------------------------------------------------
// Tensor-core flash attention — VERBATIM R7 (validated).
// ---------------------------------------------------------------------------
#define KPAD 72

__global__ __launch_bounds__(256, 1)
void attn_k(const float* __restrict__ logd, const int* __restrict__ pW)
{
    __shared__ __align__(16) __nv_bfloat16 Ksh[64 * KPAD];
    __shared__ __align__(16) __nv_bfloat16 Ksl[64 * KPAD];
    __shared__ __align__(16) __nv_bfloat16 Vsh[64 * KPAD];
    __shared__ __align__(16) __nv_bfloat16 Vsl[64 * KPAD];

    const int bh = blockIdx.y;
    const int b = bh >> 3, h = bh & 7;
    const int q0 = blockIdx.x << 7;
    const int tid = threadIdx.x;
    const int wid = tid >> 5, lane = tid & 31;
    const int g = lane >> 2, t = lane & 3;

    const int Wg = pW ? *pW : 32;
    const float invW = 1.0f / (float)Wg;
    const float decay = log1pf(expf(logd[h]));
    const float scale = 0.125f;

    const size_t kbase  = (size_t)bh * NN * HDD;

    const int qrow0 = q0 + (wid << 4) + g;
    const int qrow1 = qrow0 + 8;
    uint32_t qh[4][4], ql[4][4];
#pragma unroll
    for (int kc = 0; kc < 4; kc++) {
        int c0 = kc * 16 + 2 * t;
        qh[kc][0] = *(const uint32_t*)(gq_hi + kbase + (size_t)qrow0 * HDD + c0);
        qh[kc][1] = *(const uint32_t*)(gq_hi + kbase + (size_t)qrow1 * HDD + c0);
        qh[kc][2] = *(const uint32_t*)(gq_hi + kbase + (size_t)qrow0 * HDD + c0 + 8);
        qh[kc][3] = *(const uint32_t*)(gq_hi + kbase + (size_t)qrow1 * HDD + c0 + 8);
        ql[kc][0] = *(const uint32_t*)(gq_lo + kbase + (size_t)qrow0 * HDD + c0);
        ql[kc][1] = *(const uint32_t*)(gq_lo + kbase + (size_t)qrow1 * HDD + c0);
        ql[kc][2] = *(const uint32_t*)(gq_lo + kbase + (size_t)qrow0 * HDD + c0 + 8);
        ql[kc][3] = *(const uint32_t*)(gq_lo + kbase + (size_t)qrow1 * HDD + c0 + 8);
    }

    int qri0 = (int)(((float)qrow0 + 0.5f) * invW);
    int qri1 = (int)(((float)qrow1 + 0.5f) * invW);
    const float qr0 = (float)qri0, qc0 = (float)(qrow0 - qri0 * Wg);
    const float qr1 = (float)qri1, qc1 = (float)(qrow1 - qri1 * Wg);

    float mg0 = -1e30f, lg0 = 0.f, mg1 = -1e30f, lg1 = 0.f;
    float accO[8][4];
#pragma unroll
    for (int ni = 0; ni < 8; ni++)
#pragma unroll
        for (int c = 0; c < 4; c++) accO[ni][c] = 0.f;

    for (int tk = 0; tk < 16; tk++) {
        const int k0 = tk << 6;
#pragma unroll
        for (int i = 0; i < 2; i++) {
            int idx = tid + (i << 8);
            int row = idx >> 3, cu = (idx & 7) << 3;
            *(uint4*)(Ksh + row * KPAD + cu) =
                *(const uint4*)(gk_hi + kbase + (size_t)(k0 + row) * HDD + cu);
            *(uint4*)(Ksl + row * KPAD + cu) =
                *(const uint4*)(gk_lo + kbase + (size_t)(k0 + row) * HDD + cu);
            *(uint4*)(Vsh + row * KPAD + cu) =
                *(const uint4*)(gvt_hi + kbase + (size_t)row * NN + k0 + cu);
            *(uint4*)(Vsl + row * KPAD + cu) =
                *(const uint4*)(gvt_lo + kbase + (size_t)row * NN + k0 + cu);
        }
        __syncthreads();

        float S[8][4];
#pragma unroll
        for (int ni = 0; ni < 8; ni++)
#pragma unroll
            for (int c = 0; c < 4; c++) S[ni][c] = 0.f;

#pragma unroll
        for (int kc = 0; kc < 4; kc++) {
#pragma unroll
            for (int ni = 0; ni < 8; ni++) {
                const __nv_bfloat16* kh = Ksh + (ni * 8 + g) * KPAD + kc * 16 + 2 * t;
                uint32_t b0 = *(const uint32_t*)kh;
                uint32_t b1 = *(const uint32_t*)(kh + 8);
                mma4(S[ni], qh[kc], b0, b1);
                mma4(S[ni], ql[kc], b0, b1);
                const __nv_bfloat16* kl = Ksl + (ni * 8 + g) * KPAD + kc * 16 + 2 * t;
                uint32_t c0 = *(const uint32_t*)kl;
                uint32_t c1 = *(const uint32_t*)(kl + 8);
                mma4(S[ni], qh[kc], c0, c1);
            }
        }

#pragma unroll
        for (int ni = 0; ni < 8; ni++) {
            int kA = k0 + ni * 8 + 2 * t;
            int kB = kA + 1;
            int krAi = (int)(((float)kA + 0.5f) * invW);
            int krBi = (int)(((float)kB + 0.5f) * invW);
            float krA = (float)krAi, kcA = (float)(kA - krAi * Wg);
            float krB = (float)krBi, kcB = (float)(kB - krBi * Wg);
            float dA0 = fabsf(qr0 - krA) + fabsf(qc0 - kcA);
            float dB0 = fabsf(qr0 - krB) + fabsf(qc0 - kcB);
            float dA1 = fabsf(qr1 - krA) + fabsf(qc1 - kcA);
            float dB1 = fabsf(qr1 - krB) + fabsf(qc1 - kcB);
            S[ni][0] = fmaf(S[ni][0], scale, -decay * dA0);
            S[ni][1] = fmaf(S[ni][1], scale, -decay * dB0);
            S[ni][2] = fmaf(S[ni][2], scale, -decay * dA1);
            S[ni][3] = fmaf(S[ni][3], scale, -decay * dB1);
        }

        float mx0 = -1e30f, mx1 = -1e30f;
#pragma unroll
        for (int ni = 0; ni < 8; ni++) {
            mx0 = fmaxf(mx0, fmaxf(S[ni][0], S[ni][1]));
            mx1 = fmaxf(mx1, fmaxf(S[ni][2], S[ni][3]));
        }
        mx0 = fmaxf(mx0, __shfl_xor_sync(0xffffffffu, mx0, 1));
        mx0 = fmaxf(mx0, __shfl_xor_sync(0xffffffffu, mx0, 2));
        mx1 = fmaxf(mx1, __shfl_xor_sync(0xffffffffu, mx1, 1));
        mx1 = fmaxf(mx1, __shfl_xor_sync(0xffffffffu, mx1, 2));
        float nm0 = fmaxf(mg0, mx0), nm1 = fmaxf(mg1, mx1);
        float al0 = __expf(mg0 - nm0), al1 = __expf(mg1 - nm1);
        float sum0 = 0.f, sum1 = 0.f;
#pragma unroll
        for (int ni = 0; ni < 8; ni++) {
            S[ni][0] = __expf(S[ni][0] - nm0); sum0 += S[ni][0];
            S[ni][1] = __expf(S[ni][1] - nm0); sum0 += S[ni][1];
            S[ni][2] = __expf(S[ni][2] - nm1); sum1 += S[ni][2];
            S[ni][3] = __expf(S[ni][3] - nm1); sum1 += S[ni][3];
        }
        sum0 += __shfl_xor_sync(0xffffffffu, sum0, 1);
        sum0 += __shfl_xor_sync(0xffffffffu, sum0, 2);
        sum1 += __shfl_xor_sync(0xffffffffu, sum1, 1);
        sum1 += __shfl_xor_sync(0xffffffffu, sum1, 2);
        lg0 = lg0 * al0 + sum0;  mg0 = nm0;
        lg1 = lg1 * al1 + sum1;  mg1 = nm1;
#pragma unroll
        for (int ni = 0; ni < 8; ni++) {
            accO[ni][0] *= al0; accO[ni][1] *= al0;
            accO[ni][2] *= al1; accO[ni][3] *= al1;
        }

#pragma unroll
        for (int kc = 0; kc < 4; kc++) {
            const int nA = 2 * kc, nB = 2 * kc + 1;
            uint32_t ph[4], pl[4];
            split2(S[nA][0], S[nA][1], ph[0], pl[0]);
            split2(S[nA][2], S[nA][3], ph[1], pl[1]);
            split2(S[nB][0], S[nB][1], ph[2], pl[2]);
            split2(S[nB][2], S[nB][3], ph[3], pl[3]);
#pragma unroll
            for (int ni = 0; ni < 8; ni++) {
                const __nv_bfloat16* vh = Vsh + (ni * 8 + g) * KPAD + kc * 16 + 2 * t;
                uint32_t b0 = *(const uint32_t*)vh;
                uint32_t b1 = *(const uint32_t*)(vh + 8);
                mma4(accO[ni], ph, b0, b1);
                mma4(accO[ni], pl, b0, b1);
                const __nv_bfloat16* vl = Vsl + (ni * 8 + g) * KPAD + kc * 16 + 2 * t;
                uint32_t c0 = *(const uint32_t*)vl;
                uint32_t c1 = *(const uint32_t*)(vl + 8);
                mma4(accO[ni], ph, c0, c1);
            }
        }
        __syncthreads();
    }

    const float inv0 = 1.f / lg0;
    const float inv1 = 1.f / lg1;
#pragma unroll
    for (int ni = 0; ni < 8; ni++) {
        int d = ni * 8 + 2 * t;
        uint32_t hiA, loA, hiB, loB;
        split2(accO[ni][0] * inv0, accO[ni][1] * inv0, hiA, loA);
        split2(accO[ni][2] * inv1, accO[ni][3] * inv1, hiB, loB);
        size_t o0 = ((size_t)(b * NN + qrow0)) * DIMC + h * HDD + d;
        size_t o1 = ((size_t)(b * NN + qrow1)) * DIMC + h * HDD + d;
        *(uint32_t*)(go_hi + o0) = hiA;
        *(uint32_t*)(go_lo + o0) = loA;
        *(uint32_t*)(go_hi + o1) = hiB;
        *(uint32_t*)(go_lo + o1) = loB;
    }
}

// ---------------------------------------------------------------------------
extern "C" void kernel_launch(void* const* d_in, const int* in_sizes, int n_in,
                              void* d_out, int out_size)
{
    const float* x      = (const float*)d_in[0];
    const float* w_qkv  = (const float*)d_in[1];
    const float* w_proj = (const float*)d_in[2];
    const float* logd   = (const float*)d_in[3];
    const int*   pW     = (n_in > 5) ? (const int*)d_in[5] : nullptr;
    float* out = (float*)d_out;

    cvt_k<0><<<(MTOT * DIMC / 4 + 255) / 256, 256>>>(x, MTOT * DIMC);
    cvt_k<1><<<(3 * DIMC * DIMC / 4 + 255) / 256, 256>>>(w_qkv, 3 * DIMC * DIMC);
    cvt_k<2><<<(DIMC * DIMC / 4 + 255) / 256, 256>>>(w_proj, DIMC * DIMC);

    hgemm_k<0><<<dim3(24, 64), 256>>>(nullptr);
    attn_k<<<dim3(8, 64), 256>>>(logd, pW);
    hgemm_k<1><<<dim3(8, 64), 256>>>(out);
}

// round 9
// speedup vs baseline: 3.4378x; 1.2381x over previous
#include <cuda_runtime.h>
#include <cuda_bf16.h>
#include <cstdint>
#include <math.h>

#define DIMC 512
#define NHD  8
#define HDD  64
#define BB   8
#define NN   1024
#define MTOT (BB*NN)   // 8192
#define QKV  (BB*NHD*NN*HDD)

// ---------------- scratch (allocation-free) ----------------
__device__ __align__(16) __nv_bfloat16 gx_hi[MTOT*DIMC],  gx_lo[MTOT*DIMC];
__device__ __align__(16) __nv_bfloat16 gwq_hi[3*DIMC*DIMC], gwq_lo[3*DIMC*DIMC];
__device__ __align__(16) __nv_bfloat16 gwp_hi[DIMC*DIMC],  gwp_lo[DIMC*DIMC];
__device__ __align__(16) __nv_bfloat16 gq_hi[QKV],  gq_lo[QKV];    // [bh][n][d]
__device__ __align__(16) __nv_bfloat16 gk_hi[QKV],  gk_lo[QKV];    // [bh][n][d]
__device__ __align__(16) __nv_bfloat16 gvt_hi[QKV], gvt_lo[QKV];   // [bh][d][n]
__device__ __align__(16) __nv_bfloat16 go_hi[MTOT*DIMC], go_lo[MTOT*DIMC];

// ---------------- fp32 -> bf16 hi/lo split ----------------
template<int DST>
__global__ void cvt_k(const float* __restrict__ s, int n)
{
    __nv_bfloat16* hi;
    __nv_bfloat16* lo;
    if (DST == 0)      { hi = gx_hi;  lo = gx_lo;  }
    else if (DST == 1) { hi = gwq_hi; lo = gwq_lo; }
    else               { hi = gwp_hi; lo = gwp_lo; }

    int i = (blockIdx.x * blockDim.x + threadIdx.x) * 4;
    if (i >= n) return;
    float4 v = *(const float4*)(s + i);
    __nv_bfloat16 h0 = __float2bfloat16(v.x);
    __nv_bfloat16 h1 = __float2bfloat16(v.y);
    __nv_bfloat16 h2 = __float2bfloat16(v.z);
    __nv_bfloat16 h3 = __float2bfloat16(v.w);
    __nv_bfloat162 hp0; hp0.x = h0; hp0.y = h1;
    __nv_bfloat162 hp1; hp1.x = h2; hp1.y = h3;
    __nv_bfloat162 lp0;
    lp0.x = __float2bfloat16(v.x - __bfloat162float(h0));
    lp0.y = __float2bfloat16(v.y - __bfloat162float(h1));
    __nv_bfloat162 lp1;
    lp1.x = __float2bfloat16(v.z - __bfloat162float(h2));
    lp1.y = __float2bfloat16(v.w - __bfloat162float(h3));
    *(__nv_bfloat162*)(hi + i)     = hp0;
    *(__nv_bfloat162*)(hi + i + 2) = hp1;
    *(__nv_bfloat162*)(lo + i)     = lp0;
    *(__nv_bfloat162*)(lo + i + 2) = lp1;
}

// ---------------- helpers ----------------
__device__ __forceinline__ void mma4(float* c, const uint32_t* a,
                                     uint32_t b0, uint32_t b1)
{
    asm volatile(
        "mma.sync.aligned.m16n8k16.row.col.f32.bf16.bf16.f32 "
        "{%0,%1,%2,%3}, {%4,%5,%6,%7}, {%8,%9}, {%0,%1,%2,%3};"
        : "+f"(c[0]), "+f"(c[1]), "+f"(c[2]), "+f"(c[3])
        : "r"(a[0]), "r"(a[1]), "r"(a[2]), "r"(a[3]), "r"(b0), "r"(b1));
}

__device__ __forceinline__ void ldsm4(uint32_t* r, const void* p)
{
    uint32_t a = (uint32_t)__cvta_generic_to_shared(p);
    asm volatile("ldmatrix.sync.aligned.m8n8.x4.shared.b16 {%0,%1,%2,%3}, [%4];"
                 : "=r"(r[0]), "=r"(r[1]), "=r"(r[2]), "=r"(r[3]) : "r"(a));
}

__device__ __forceinline__ void split2(float v0, float v1,
                                       uint32_t& hi, uint32_t& lo)
{
    __nv_bfloat16 hx = __float2bfloat16(v0);
    __nv_bfloat16 hy = __float2bfloat16(v1);
    __nv_bfloat162 hp; hp.x = hx; hp.y = hy;
    hi = *(uint32_t*)&hp;
    __nv_bfloat162 lp;
    lp.x = __float2bfloat16(v0 - __bfloat162float(hx));
    lp.y = __float2bfloat16(v1 - __bfloat162float(hy));
    lo = *(uint32_t*)&lp;
}

__device__ __forceinline__ void cpa16(void* smem, const void* gmem)
{
    uint32_t s = (uint32_t)__cvta_generic_to_shared(smem);
    asm volatile("cp.async.ca.shared.global [%0], [%1], 16;"
                 :: "r"(s), "l"(gmem));
}
__device__ __forceinline__ void cpa_commit()
{ asm volatile("cp.async.commit_group;" ::: "memory"); }
template<int N>
__device__ __forceinline__ void cpa_wait()
{ asm volatile("cp.async.wait_group %0;" :: "n"(N) : "memory"); }

// ---------------------------------------------------------------------------
// HMMA GEMM, 3-stage cp.async pipeline, 128x128 block tile, ldmatrix frags.
// C[M,NC] = A[M,512] @ W[NC,512]^T, split-bf16: Ah Bh + Al Bh + Ah Bl.
// 8 warps = 4m x 2n; warp tile 32x64; K-chunk 32.
// ---------------------------------------------------------------------------
#define LDA_S 40
#define NCHUNK 48
#define STAGE_E (2 * 128 * LDA_S)              // A + B elements per stage
#define SMEM_BYTES (3 * STAGE_E * 2)           // 61440 bytes

template<int MODE>
__global__ __launch_bounds__(256, 2)
void hgemm_k(float* __restrict__ Cout)
{
    extern __shared__ __align__(16) __nv_bfloat16 smem[];

    const int tid = threadIdx.x;
    const int wid = tid >> 5, lane = tid & 31;
    const int g = lane >> 2, t = lane & 3;
    const int m0 = blockIdx.y << 7;
    const int n0 = blockIdx.x << 7;
    const int wm = (wid & 3) << 5;     // 4 m-warps x 32 rows
    const int wn = (wid >> 2) << 6;    // 2 n-warps x 64 cols

    const __nv_bfloat16* a_hi = (MODE == 0) ? gx_hi : go_hi;
    const __nv_bfloat16* a_lo = (MODE == 0) ? gx_lo : go_lo;
    const __nv_bfloat16* b_hi = (MODE == 0) ? gwq_hi : gwp_hi;
    const __nv_bfloat16* b_lo = (MODE == 0) ? gwq_lo : gwp_lo;

    // staging coords: 128 rows x 4x16B units, 2 per thread for A and B each
    const int srow = tid >> 2, scu = (tid & 3) << 3;

    // ldmatrix lane offsets
    const int a_r = (lane & 7) + ((lane >> 3) & 1) * 8;   // row within 16
    const int a_c = (lane >> 4) * 8;                      // k half
    const int b_r = (lane & 7) + (lane >> 4) * 8;         // row within ni pair
    const int b_c = ((lane >> 3) & 1) * 8;                // k half

    auto As = [&](int s) { return smem + s * STAGE_E; };
    auto Bs = [&](int s) { return smem + s * STAGE_E + 128 * LDA_S; };

    auto load_chunk = [&](int c, int s) {
        const int pass = c >> 4;
        const int kc = (c & 15) << 5;
        const __nv_bfloat16* asrc = (pass == 1) ? a_lo : a_hi;
        const __nv_bfloat16* bsrc = (pass == 2) ? b_lo : b_hi;
        __nv_bfloat16* as_ = As(s);
        __nv_bfloat16* bs_ = Bs(s);
#pragma unroll
        for (int i = 0; i < 2; i++) {
            int row = srow + (i << 6);
            cpa16(as_ + row * LDA_S + scu,
                  asrc + (size_t)(m0 + row) * DIMC + kc + scu);
            cpa16(bs_ + row * LDA_S + scu,
                  bsrc + (size_t)(n0 + row) * DIMC + kc + scu);
        }
        cpa_commit();
    };

    float acc[2][8][4];
#pragma unroll
    for (int mi = 0; mi < 2; mi++)
#pragma unroll
        for (int ni = 0; ni < 8; ni++)
#pragma unroll
            for (int c = 0; c < 4; c++) acc[mi][ni][c] = 0.f;

    load_chunk(0, 0);
    load_chunk(1, 1);

    for (int c = 0; c < NCHUNK; c++) {
        const int s = c % 3;
        if (c + 1 < NCHUNK) cpa_wait<1>(); else cpa_wait<0>();
        __syncthreads();
        if (c + 2 < NCHUNK) load_chunk(c + 2, (c + 2) % 3);

        const __nv_bfloat16* Ab = As(s);
        const __nv_bfloat16* Bb = Bs(s);
#pragma unroll
        for (int ks = 0; ks < 2; ks++) {
            const int k0 = ks << 4;
            uint32_t af[2][4];
            ldsm4(af[0], Ab + (wm + a_r) * LDA_S + k0 + a_c);
            ldsm4(af[1], Ab + (wm + 16 + a_r) * LDA_S + k0 + a_c);
#pragma unroll
            for (int np = 0; np < 4; np++) {
                uint32_t bq[4];
                ldsm4(bq, Bb + (wn + np * 16 + b_r) * LDA_S + k0 + b_c);
                mma4(acc[0][np * 2],     af[0], bq[0], bq[1]);
                mma4(acc[1][np * 2],     af[1], bq[0], bq[1]);
                mma4(acc[0][np * 2 + 1], af[0], bq[2], bq[3]);
                mma4(acc[1][np * 2 + 1], af[1], bq[2], bq[3]);
            }
        }
    }

    // -------- epilogue --------
    if (MODE == 0) {
#pragma unroll
        for (int mi = 0; mi < 2; mi++)
#pragma unroll
            for (int ni = 0; ni < 8; ni++) {
                int gm  = m0 + wm + (mi << 4) + g;
                int gm2 = gm + 8;
                int col = n0 + wn + (ni << 3) + 2 * t;
                int which = col >> 9;
                int h = (col >> 6) & (NHD - 1);
                int d = col & (HDD - 1);
                int b1_ = gm >> 10,  n1_ = gm & (NN - 1);
                int b2_ = gm2 >> 10, n2_ = gm2 & (NN - 1);
                uint32_t hiA, loA, hiB, loB;
                split2(acc[mi][ni][0], acc[mi][ni][1], hiA, loA);
                split2(acc[mi][ni][2], acc[mi][ni][3], hiB, loB);
                if (which == 2) {
                    __nv_bfloat162 hA = *(__nv_bfloat162*)&hiA;
                    __nv_bfloat162 lA = *(__nv_bfloat162*)&loA;
                    __nv_bfloat162 hB = *(__nv_bfloat162*)&hiB;
                    __nv_bfloat162 lB = *(__nv_bfloat162*)&loB;
                    size_t vb1 = ((size_t)((b1_ * NHD + h) * HDD + d)) * NN + n1_;
                    gvt_hi[vb1]      = hA.x; gvt_lo[vb1]      = lA.x;
                    gvt_hi[vb1 + NN] = hA.y; gvt_lo[vb1 + NN] = lA.y;
                    size_t vb2 = ((size_t)((b2_ * NHD + h) * HDD + d)) * NN + n2_;
                    gvt_hi[vb2]      = hB.x; gvt_lo[vb2]      = lB.x;
                    gvt_hi[vb2 + NN] = hB.y; gvt_lo[vb2 + NN] = lB.y;
                } else {
                    __nv_bfloat16* dh = which ? gk_hi : gq_hi;
                    __nv_bfloat16* dl = which ? gk_lo : gq_lo;
                    size_t qb1 = ((size_t)((b1_ * NHD + h) * NN + n1_)) * HDD + d;
                    *(uint32_t*)(dh + qb1) = hiA;
                    *(uint32_t*)(dl + qb1) = loA;
                    size_t qb2 = ((size_t)((b2_ * NHD + h) * NN + n2_)) * HDD + d;
                    *(uint32_t*)(dh + qb2) = hiB;
                    *(uint32_t*)(dl + qb2) = loB;
                }
            }
    } else {
#pragma unroll
        for (int mi = 0; mi < 2; mi++)
#pragma unroll
            for (int ni = 0; ni < 8; ni++) {
                int gm = m0 + wm + (mi << 4) + g;
                int cc = n0 + wn + (ni << 3) + 2 * t;
                *(float2*)(Cout + (size_t)gm * DIMC + cc) =
                    make_float2(acc[mi][ni][0], acc[mi][ni][1]);
                *(float2*)(Cout + (size_t)(gm + 8) * DIMC + cc) =
                    make_float2(acc[mi][ni][2], acc[mi][ni][3]);
            }
    }
}

// ---------------------------------------------------------------------------
// Tensor-core flash attention — VERBATIM R7/R8 (validated).
// ---------------------------------------------------------------------------
#define KPAD 72

__global__ __launch_bounds__(256, 1)
void attn_k(const float* __restrict__ logd, const int* __restrict__ pW)
{
    __shared__ __align__(16) __nv_bfloat16 Ksh[64 * KPAD];
    __shared__ __align__(16) __nv_bfloat16 Ksl[64 * KPAD];
    __shared__ __align__(16) __nv_bfloat16 Vsh[64 * KPAD];
    __shared__ __align__(16) __nv_bfloat16 Vsl[64 * KPAD];

    const int bh = blockIdx.y;
    const int b = bh >> 3, h = bh & 7;
    const int q0 = blockIdx.x << 7;
    const int tid = threadIdx.x;
    const int wid = tid >> 5, lane = tid & 31;
    const int g = lane >> 2, t = lane & 3;

    const int Wg = pW ? *pW : 32;
    const float invW = 1.0f / (float)Wg;
    const float decay = log1pf(expf(logd[h]));
    const float scale = 0.125f;

    const size_t kbase  = (size_t)bh * NN * HDD;

    const int qrow0 = q0 + (wid << 4) + g;
    const int qrow1 = qrow0 + 8;
    uint32_t qh[4][4], ql[4][4];
#pragma unroll
    for (int kc = 0; kc < 4; kc++) {
        int c0 = kc * 16 + 2 * t;
        qh[kc][0] = *(const uint32_t*)(gq_hi + kbase + (size_t)qrow0 * HDD + c0);
        qh[kc][1] = *(const uint32_t*)(gq_hi + kbase + (size_t)qrow1 * HDD + c0);
        qh[kc][2] = *(const uint32_t*)(gq_hi + kbase + (size_t)qrow0 * HDD + c0 + 8);
        qh[kc][3] = *(const uint32_t*)(gq_hi + kbase + (size_t)qrow1 * HDD + c0 + 8);
        ql[kc][0] = *(const uint32_t*)(gq_lo + kbase + (size_t)qrow0 * HDD + c0);
        ql[kc][1] = *(const uint32_t*)(gq_lo + kbase + (size_t)qrow1 * HDD + c0);
        ql[kc][2] = *(const uint32_t*)(gq_lo + kbase + (size_t)qrow0 * HDD + c0 + 8);
        ql[kc][3] = *(const uint32_t*)(gq_lo + kbase + (size_t)qrow1 * HDD + c0 + 8);
    }

    int qri0 = (int)(((float)qrow0 + 0.5f) * invW);
    int qri1 = (int)(((float)qrow1 + 0.5f) * invW);
    const float qr0 = (float)qri0, qc0 = (float)(qrow0 - qri0 * Wg);
    const float qr1 = (float)qri1, qc1 = (float)(qrow1 - qri1 * Wg);

    float mg0 = -1e30f, lg0 = 0.f, mg1 = -1e30f, lg1 = 0.f;
    float accO[8][4];
#pragma unroll
    for (int ni = 0; ni < 8; ni++)
#pragma unroll
        for (int c = 0; c < 4; c++) accO[ni][c] = 0.f;

    for (int tk = 0; tk < 16; tk++) {
        const int k0 = tk << 6;
#pragma unroll
        for (int i = 0; i < 2; i++) {
            int idx = tid + (i << 8);
            int row = idx >> 3, cu = (idx & 7) << 3;
            *(uint4*)(Ksh + row * KPAD + cu) =
                *(const uint4*)(gk_hi + kbase + (size_t)(k0 + row) * HDD + cu);
            *(uint4*)(Ksl + row * KPAD + cu) =
                *(const uint4*)(gk_lo + kbase + (size_t)(k0 + row) * HDD + cu);
            *(uint4*)(Vsh + row * KPAD + cu) =
                *(const uint4*)(gvt_hi + kbase + (size_t)row * NN + k0 + cu);
            *(uint4*)(Vsl + row * KPAD + cu) =
                *(const uint4*)(gvt_lo + kbase + (size_t)row * NN + k0 + cu);
        }
        __syncthreads();

        float S[8][4];
#pragma unroll
        for (int ni = 0; ni < 8; ni++)
#pragma unroll
            for (int c = 0; c < 4; c++) S[ni][c] = 0.f;

#pragma unroll
        for (int kc = 0; kc < 4; kc++) {
#pragma unroll
            for (int ni = 0; ni < 8; ni++) {
                const __nv_bfloat16* kh = Ksh + (ni * 8 + g) * KPAD + kc * 16 + 2 * t;
                uint32_t b0 = *(const uint32_t*)kh;
                uint32_t b1 = *(const uint32_t*)(kh + 8);
                mma4(S[ni], qh[kc], b0, b1);
                mma4(S[ni], ql[kc], b0, b1);
                const __nv_bfloat16* kl = Ksl + (ni * 8 + g) * KPAD + kc * 16 + 2 * t;
                uint32_t c0 = *(const uint32_t*)kl;
                uint32_t c1 = *(const uint32_t*)(kl + 8);
                mma4(S[ni], qh[kc], c0, c1);
            }
        }

#pragma unroll
        for (int ni = 0; ni < 8; ni++) {
            int kA = k0 + ni * 8 + 2 * t;
            int kB = kA + 1;
            int krAi = (int)(((float)kA + 0.5f) * invW);
            int krBi = (int)(((float)kB + 0.5f) * invW);
            float krA = (float)krAi, kcA = (float)(kA - krAi * Wg);
            float krB = (float)krBi, kcB = (float)(kB - krBi * Wg);
            float dA0 = fabsf(qr0 - krA) + fabsf(qc0 - kcA);
            float dB0 = fabsf(qr0 - krB) + fabsf(qc0 - kcB);
            float dA1 = fabsf(qr1 - krA) + fabsf(qc1 - kcA);
            float dB1 = fabsf(qr1 - krB) + fabsf(qc1 - kcB);
            S[ni][0] = fmaf(S[ni][0], scale, -decay * dA0);
            S[ni][1] = fmaf(S[ni][1], scale, -decay * dB0);
            S[ni][2] = fmaf(S[ni][2], scale, -decay * dA1);
            S[ni][3] = fmaf(S[ni][3], scale, -decay * dB1);
        }

        float mx0 = -1e30f, mx1 = -1e30f;
#pragma unroll
        for (int ni = 0; ni < 8; ni++) {
            mx0 = fmaxf(mx0, fmaxf(S[ni][0], S[ni][1]));
            mx1 = fmaxf(mx1, fmaxf(S[ni][2], S[ni][3]));
        }
        mx0 = fmaxf(mx0, __shfl_xor_sync(0xffffffffu, mx0, 1));
        mx0 = fmaxf(mx0, __shfl_xor_sync(0xffffffffu, mx0, 2));
        mx1 = fmaxf(mx1, __shfl_xor_sync(0xffffffffu, mx1, 1));
        mx1 = fmaxf(mx1, __shfl_xor_sync(0xffffffffu, mx1, 2));
        float nm0 = fmaxf(mg0, mx0), nm1 = fmaxf(mg1, mx1);
        float al0 = __expf(mg0 - nm0), al1 = __expf(mg1 - nm1);
        float sum0 = 0.f, sum1 = 0.f;
#pragma unroll
        for (int ni = 0; ni < 8; ni++) {
            S[ni][0] = __expf(S[ni][0] - nm0); sum0 += S[ni][0];
            S[ni][1] = __expf(S[ni][1] - nm0); sum0 += S[ni][1];
            S[ni][2] = __expf(S[ni][2] - nm1); sum1 += S[ni][2];
            S[ni][3] = __expf(S[ni][3] - nm1); sum1 += S[ni][3];
        }
        sum0 += __shfl_xor_sync(0xffffffffu, sum0, 1);
        sum0 += __shfl_xor_sync(0xffffffffu, sum0, 2);
        sum1 += __shfl_xor_sync(0xffffffffu, sum1, 1);
        sum1 += __shfl_xor_sync(0xffffffffu, sum1, 2);
        lg0 = lg0 * al0 + sum0;  mg0 = nm0;
        lg1 = lg1 * al1 + sum1;  mg1 = nm1;
#pragma unroll
        for (int ni = 0; ni < 8; ni++) {
            accO[ni][0] *= al0; accO[ni][1] *= al0;
            accO[ni][2] *= al1; accO[ni][3] *= al1;
        }

#pragma unroll
        for (int kc = 0; kc < 4; kc++) {
            const int nA = 2 * kc, nB = 2 * kc + 1;
            uint32_t ph[4], pl[4];
            split2(S[nA][0], S[nA][1], ph[0], pl[0]);
            split2(S[nA][2], S[nA][3], ph[1], pl[1]);
            split2(S[nB][0], S[nB][1], ph[2], pl[2]);
            split2(S[nB][2], S[nB][3], ph[3], pl[3]);
#pragma unroll
            for (int ni = 0; ni < 8; ni++) {
                const __nv_bfloat16* vh = Vsh + (ni * 8 + g) * KPAD + kc * 16 + 2 * t;
                uint32_t b0 = *(const uint32_t*)vh;
                uint32_t b1 = *(const uint32_t*)(vh + 8);
                mma4(accO[ni], ph, b0, b1);
                mma4(accO[ni], pl, b0, b1);
                const __nv_bfloat16* vl = Vsl + (ni * 8 + g) * KPAD + kc * 16 + 2 * t;
                uint32_t c0 = *(const uint32_t*)vl;
                uint32_t c1 = *(const uint32_t*)(vl + 8);
                mma4(accO[ni], ph, c0, c1);
            }
        }
        __syncthreads();
    }

    const float inv0 = 1.f / lg0;
    const float inv1 = 1.f / lg1;
#pragma unroll
    for (int ni = 0; ni < 8; ni++) {
        int d = ni * 8 + 2 * t;
        uint32_t hiA, loA, hiB, loB;
        split2(accO[ni][0] * inv0, accO[ni][1] * inv0, hiA, loA);
        split2(accO[ni][2] * inv1, accO[ni][3] * inv1, hiB, loB);
        size_t o0 = ((size_t)(b * NN + qrow0)) * DIMC + h * HDD + d;
        size_t o1 = ((size_t)(b * NN + qrow1)) * DIMC + h * HDD + d;
        *(uint32_t*)(go_hi + o0) = hiA;
        *(uint32_t*)(go_lo + o0) = loA;
        *(uint32_t*)(go_hi + o1) = hiB;
        *(uint32_t*)(go_lo + o1) = loB;
    }
}

// ---------------------------------------------------------------------------
extern "C" void kernel_launch(void* const* d_in, const int* in_sizes, int n_in,
                              void* d_out, int out_size)
{
    const float* x      = (const float*)d_in[0];
    const float* w_qkv  = (const float*)d_in[1];
    const float* w_proj = (const float*)d_in[2];
    const float* logd   = (const float*)d_in[3];
    const int*   pW     = (n_in > 5) ? (const int*)d_in[5] : nullptr;
    float* out = (float*)d_out;

    cudaFuncSetAttribute(hgemm_k<0>, cudaFuncAttributeMaxDynamicSharedMemorySize, SMEM_BYTES);
    cudaFuncSetAttribute(hgemm_k<1>, cudaFuncAttributeMaxDynamicSharedMemorySize, SMEM_BYTES);

    cvt_k<0><<<(MTOT * DIMC / 4 + 255) / 256, 256>>>(x, MTOT * DIMC);
    cvt_k<1><<<(3 * DIMC * DIMC / 4 + 255) / 256, 256>>>(w_qkv, 3 * DIMC * DIMC);
    cvt_k<2><<<(DIMC * DIMC / 4 + 255) / 256, 256>>>(w_proj, DIMC * DIMC);

    hgemm_k<0><<<dim3(12, 64), 256, SMEM_BYTES>>>(nullptr);
    attn_k<<<dim3(8, 64), 256>>>(logd, pW);
    hgemm_k<1><<<dim3(4, 64), 256, SMEM_BYTES>>>(out);
}

// round 10
// speedup vs baseline: 3.8106x; 1.1084x over previous
#include <cuda_runtime.h>
#include <cuda_bf16.h>
#include <cstdint>
#include <math.h>

#define DIMC 512
#define NHD  8
#define HDD  64
#define BB   8
#define NN   1024
#define MTOT (BB*NN)   // 8192
#define QKV  (BB*NHD*NN*HDD)

// ---------------- scratch (allocation-free) ----------------
__device__ __align__(16) __nv_bfloat16 gx_hi[MTOT*DIMC],  gx_lo[MTOT*DIMC];
__device__ __align__(16) __nv_bfloat16 gwq_hi[3*DIMC*DIMC], gwq_lo[3*DIMC*DIMC];
__device__ __align__(16) __nv_bfloat16 gwp_hi[DIMC*DIMC],  gwp_lo[DIMC*DIMC];
__device__ __align__(16) __nv_bfloat16 gq_hi[QKV],  gq_lo[QKV];    // [bh][n][d]
__device__ __align__(16) __nv_bfloat16 gk_hi[QKV],  gk_lo[QKV];    // [bh][n][d]
__device__ __align__(16) __nv_bfloat16 gvt_hi[QKV], gvt_lo[QKV];   // [bh][d][n]
__device__ __align__(16) __nv_bfloat16 go_hi[MTOT*DIMC], go_lo[MTOT*DIMC];

// ---------------- fp32 -> bf16 hi/lo split ----------------
template<int DST>
__global__ void cvt_k(const float* __restrict__ s, int n)
{
    __nv_bfloat16* hi;
    __nv_bfloat16* lo;
    if (DST == 0)      { hi = gx_hi;  lo = gx_lo;  }
    else if (DST == 1) { hi = gwq_hi; lo = gwq_lo; }
    else               { hi = gwp_hi; lo = gwp_lo; }

    int i = (blockIdx.x * blockDim.x + threadIdx.x) * 4;
    if (i >= n) return;
    float4 v = *(const float4*)(s + i);
    __nv_bfloat16 h0 = __float2bfloat16(v.x);
    __nv_bfloat16 h1 = __float2bfloat16(v.y);
    __nv_bfloat16 h2 = __float2bfloat16(v.z);
    __nv_bfloat16 h3 = __float2bfloat16(v.w);
    __nv_bfloat162 hp0; hp0.x = h0; hp0.y = h1;
    __nv_bfloat162 hp1; hp1.x = h2; hp1.y = h3;
    __nv_bfloat162 lp0;
    lp0.x = __float2bfloat16(v.x - __bfloat162float(h0));
    lp0.y = __float2bfloat16(v.y - __bfloat162float(h1));
    __nv_bfloat162 lp1;
    lp1.x = __float2bfloat16(v.z - __bfloat162float(h2));
    lp1.y = __float2bfloat16(v.w - __bfloat162float(h3));
    *(__nv_bfloat162*)(hi + i)     = hp0;
    *(__nv_bfloat162*)(hi + i + 2) = hp1;
    *(__nv_bfloat162*)(lo + i)     = lp0;
    *(__nv_bfloat162*)(lo + i + 2) = lp1;
}

// ---------------- helpers ----------------
__device__ __forceinline__ void mma4(float* c, const uint32_t* a,
                                     uint32_t b0, uint32_t b1)
{
    asm volatile(
        "mma.sync.aligned.m16n8k16.row.col.f32.bf16.bf16.f32 "
        "{%0,%1,%2,%3}, {%4,%5,%6,%7}, {%8,%9}, {%0,%1,%2,%3};"
        : "+f"(c[0]), "+f"(c[1]), "+f"(c[2]), "+f"(c[3])
        : "r"(a[0]), "r"(a[1]), "r"(a[2]), "r"(a[3]), "r"(b0), "r"(b1));
}

__device__ __forceinline__ void ldsm4(uint32_t* r, const void* p)
{
    uint32_t a = (uint32_t)__cvta_generic_to_shared(p);
    asm volatile("ldmatrix.sync.aligned.m8n8.x4.shared.b16 {%0,%1,%2,%3}, [%4];"
                 : "=r"(r[0]), "=r"(r[1]), "=r"(r[2]), "=r"(r[3]) : "r"(a));
}

__device__ __forceinline__ void split2(float v0, float v1,
                                       uint32_t& hi, uint32_t& lo)
{
    __nv_bfloat16 hx = __float2bfloat16(v0);
    __nv_bfloat16 hy = __float2bfloat16(v1);
    __nv_bfloat162 hp; hp.x = hx; hp.y = hy;
    hi = *(uint32_t*)&hp;
    __nv_bfloat162 lp;
    lp.x = __float2bfloat16(v0 - __bfloat162float(hx));
    lp.y = __float2bfloat16(v1 - __bfloat162float(hy));
    lo = *(uint32_t*)&lp;
}

__device__ __forceinline__ void cpa16(void* smem, const void* gmem)
{
    uint32_t s = (uint32_t)__cvta_generic_to_shared(smem);
    asm volatile("cp.async.ca.shared.global [%0], [%1], 16;"
                 :: "r"(s), "l"(gmem));
}
__device__ __forceinline__ void cpa_commit()
{ asm volatile("cp.async.commit_group;" ::: "memory"); }
template<int N>
__device__ __forceinline__ void cpa_wait()
{ asm volatile("cp.async.wait_group %0;" :: "n"(N) : "memory"); }

// ---------------------------------------------------------------------------
// HMMA GEMM — VERBATIM R9 (validated): 3-stage cp.async, 128x128, ldmatrix.
// ---------------------------------------------------------------------------
#define LDA_S 40
#define NCHUNK 48
#define STAGE_E (2 * 128 * LDA_S)
#define SMEM_BYTES (3 * STAGE_E * 2)

template<int MODE>
__global__ __launch_bounds__(256, 2)
void hgemm_k(float* __restrict__ Cout)
{
    extern __shared__ __align__(16) __nv_bfloat16 smem[];

    const int tid = threadIdx.x;
    const int wid = tid >> 5, lane = tid & 31;
    const int g = lane >> 2, t = lane & 3;
    const int m0 = blockIdx.y << 7;
    const int n0 = blockIdx.x << 7;
    const int wm = (wid & 3) << 5;
    const int wn = (wid >> 2) << 6;

    const __nv_bfloat16* a_hi = (MODE == 0) ? gx_hi : go_hi;
    const __nv_bfloat16* a_lo = (MODE == 0) ? gx_lo : go_lo;
    const __nv_bfloat16* b_hi = (MODE == 0) ? gwq_hi : gwp_hi;
    const __nv_bfloat16* b_lo = (MODE == 0) ? gwq_lo : gwp_lo;

    const int srow = tid >> 2, scu = (tid & 3) << 3;
    const int a_r = (lane & 7) + ((lane >> 3) & 1) * 8;
    const int a_c = (lane >> 4) * 8;
    const int b_r = (lane & 7) + (lane >> 4) * 8;
    const int b_c = ((lane >> 3) & 1) * 8;

    auto As = [&](int s) { return smem + s * STAGE_E; };
    auto Bs = [&](int s) { return smem + s * STAGE_E + 128 * LDA_S; };

    auto load_chunk = [&](int c, int s) {
        const int pass = c >> 4;
        const int kc = (c & 15) << 5;
        const __nv_bfloat16* asrc = (pass == 1) ? a_lo : a_hi;
        const __nv_bfloat16* bsrc = (pass == 2) ? b_lo : b_hi;
        __nv_bfloat16* as_ = As(s);
        __nv_bfloat16* bs_ = Bs(s);
#pragma unroll
        for (int i = 0; i < 2; i++) {
            int row = srow + (i << 6);
            cpa16(as_ + row * LDA_S + scu,
                  asrc + (size_t)(m0 + row) * DIMC + kc + scu);
            cpa16(bs_ + row * LDA_S + scu,
                  bsrc + (size_t)(n0 + row) * DIMC + kc + scu);
        }
        cpa_commit();
    };

    float acc[2][8][4];
#pragma unroll
    for (int mi = 0; mi < 2; mi++)
#pragma unroll
        for (int ni = 0; ni < 8; ni++)
#pragma unroll
            for (int c = 0; c < 4; c++) acc[mi][ni][c] = 0.f;

    load_chunk(0, 0);
    load_chunk(1, 1);

    for (int c = 0; c < NCHUNK; c++) {
        const int s = c % 3;
        if (c + 1 < NCHUNK) cpa_wait<1>(); else cpa_wait<0>();
        __syncthreads();
        if (c + 2 < NCHUNK) load_chunk(c + 2, (c + 2) % 3);

        const __nv_bfloat16* Ab = As(s);
        const __nv_bfloat16* Bb = Bs(s);
#pragma unroll
        for (int ks = 0; ks < 2; ks++) {
            const int k0 = ks << 4;
            uint32_t af[2][4];
            ldsm4(af[0], Ab + (wm + a_r) * LDA_S + k0 + a_c);
            ldsm4(af[1], Ab + (wm + 16 + a_r) * LDA_S + k0 + a_c);
#pragma unroll
            for (int np = 0; np < 4; np++) {
                uint32_t bq[4];
                ldsm4(bq, Bb + (wn + np * 16 + b_r) * LDA_S + k0 + b_c);
                mma4(acc[0][np * 2],     af[0], bq[0], bq[1]);
                mma4(acc[1][np * 2],     af[1], bq[0], bq[1]);
                mma4(acc[0][np * 2 + 1], af[0], bq[2], bq[3]);
                mma4(acc[1][np * 2 + 1], af[1], bq[2], bq[3]);
            }
        }
    }

    if (MODE == 0) {
#pragma unroll
        for (int mi = 0; mi < 2; mi++)
#pragma unroll
            for (int ni = 0; ni < 8; ni++) {
                int gm  = m0 + wm + (mi << 4) + g;
                int gm2 = gm + 8;
                int col = n0 + wn + (ni << 3) + 2 * t;
                int which = col >> 9;
                int h = (col >> 6) & (NHD - 1);
                int d = col & (HDD - 1);
                int b1_ = gm >> 10,  n1_ = gm & (NN - 1);
                int b2_ = gm2 >> 10, n2_ = gm2 & (NN - 1);
                uint32_t hiA, loA, hiB, loB;
                split2(acc[mi][ni][0], acc[mi][ni][1], hiA, loA);
                split2(acc[mi][ni][2], acc[mi][ni][3], hiB, loB);
                if (which == 2) {
                    __nv_bfloat162 hA = *(__nv_bfloat162*)&hiA;
                    __nv_bfloat162 lA = *(__nv_bfloat162*)&loA;
                    __nv_bfloat162 hB = *(__nv_bfloat162*)&hiB;
                    __nv_bfloat162 lB = *(__nv_bfloat162*)&loB;
                    size_t vb1 = ((size_t)((b1_ * NHD + h) * HDD + d)) * NN + n1_;
                    gvt_hi[vb1]      = hA.x; gvt_lo[vb1]      = lA.x;
                    gvt_hi[vb1 + NN] = hA.y; gvt_lo[vb1 + NN] = lA.y;
                    size_t vb2 = ((size_t)((b2_ * NHD + h) * HDD + d)) * NN + n2_;
                    gvt_hi[vb2]      = hB.x; gvt_lo[vb2]      = lB.x;
                    gvt_hi[vb2 + NN] = hB.y; gvt_lo[vb2 + NN] = lB.y;
                } else {
                    __nv_bfloat16* dh = which ? gk_hi : gq_hi;
                    __nv_bfloat16* dl = which ? gk_lo : gq_lo;
                    size_t qb1 = ((size_t)((b1_ * NHD + h) * NN + n1_)) * HDD + d;
                    *(uint32_t*)(dh + qb1) = hiA;
                    *(uint32_t*)(dl + qb1) = loA;
                    size_t qb2 = ((size_t)((b2_ * NHD + h) * NN + n2_)) * HDD + d;
                    *(uint32_t*)(dh + qb2) = hiB;
                    *(uint32_t*)(dl + qb2) = loB;
                }
            }
    } else {
#pragma unroll
        for (int mi = 0; mi < 2; mi++)
#pragma unroll
            for (int ni = 0; ni < 8; ni++) {
                int gm = m0 + wm + (mi << 4) + g;
                int cc = n0 + wn + (ni << 3) + 2 * t;
                *(float2*)(Cout + (size_t)gm * DIMC + cc) =
                    make_float2(acc[mi][ni][0], acc[mi][ni][1]);
                *(float2*)(Cout + (size_t)(gm + 8) * DIMC + cc) =
                    make_float2(acc[mi][ni][2], acc[mi][ni][3]);
            }
    }
}

// ---------------------------------------------------------------------------
// Tensor-core flash attention, R10: 2-stage cp.async K/V pipeline + ldmatrix.
// Math/layouts identical to validated R7-R9 version.
// ---------------------------------------------------------------------------
#define KPAD 72
#define TILE_E (64 * KPAD)         // one array (K or V, hi or lo)
#define ASTAGE (4 * TILE_E)        // Khi,Klo,Vhi,Vlo per stage
#define ATTN_SMEM (2 * ASTAGE * 2) // 73728 bytes

__global__ __launch_bounds__(256, 1)
void attn_k(const float* __restrict__ logd, const int* __restrict__ pW)
{
    extern __shared__ __align__(16) __nv_bfloat16 smem[];

    const int bh = blockIdx.y;
    const int b = bh >> 3, h = bh & 7;
    const int q0 = blockIdx.x << 7;
    const int tid = threadIdx.x;
    const int wid = tid >> 5, lane = tid & 31;
    const int g = lane >> 2, t = lane & 3;
    const int b_r = (lane & 7) + (lane >> 4) * 8;
    const int b_c = ((lane >> 3) & 1) * 8;

    const int Wg = pW ? *pW : 32;
    const float invW = 1.0f / (float)Wg;
    const float decay = log1pf(expf(logd[h]));
    const float scale = 0.125f;

    const size_t kbase = (size_t)bh * NN * HDD;

    auto Khi = [&](int s) { return smem + s * ASTAGE; };
    auto Klo = [&](int s) { return smem + s * ASTAGE + TILE_E; };
    auto Vhi = [&](int s) { return smem + s * ASTAGE + 2 * TILE_E; };
    auto Vlo = [&](int s) { return smem + s * ASTAGE + 3 * TILE_E; };

    // staging: 2 iters x 4 arrays x 16B per thread
    auto load_tile = [&](int tk, int s) {
        const int k0 = tk << 6;
#pragma unroll
        for (int i = 0; i < 2; i++) {
            int idx = tid + (i << 8);
            int row = idx >> 3, cu = (idx & 7) << 3;
            cpa16(Khi(s) + row * KPAD + cu,
                  gk_hi + kbase + (size_t)(k0 + row) * HDD + cu);
            cpa16(Klo(s) + row * KPAD + cu,
                  gk_lo + kbase + (size_t)(k0 + row) * HDD + cu);
            cpa16(Vhi(s) + row * KPAD + cu,
                  gvt_hi + kbase + (size_t)row * NN + k0 + cu);
            cpa16(Vlo(s) + row * KPAD + cu,
                  gvt_lo + kbase + (size_t)row * NN + k0 + cu);
        }
        cpa_commit();
    };

    // ---- preload Q fragments (hi/lo) straight from gmem ----
    const int qrow0 = q0 + (wid << 4) + g;
    const int qrow1 = qrow0 + 8;
    uint32_t qh[4][4], ql[4][4];
#pragma unroll
    for (int kc = 0; kc < 4; kc++) {
        int c0 = kc * 16 + 2 * t;
        qh[kc][0] = *(const uint32_t*)(gq_hi + kbase + (size_t)qrow0 * HDD + c0);
        qh[kc][1] = *(const uint32_t*)(gq_hi + kbase + (size_t)qrow1 * HDD + c0);
        qh[kc][2] = *(const uint32_t*)(gq_hi + kbase + (size_t)qrow0 * HDD + c0 + 8);
        qh[kc][3] = *(const uint32_t*)(gq_hi + kbase + (size_t)qrow1 * HDD + c0 + 8);
        ql[kc][0] = *(const uint32_t*)(gq_lo + kbase + (size_t)qrow0 * HDD + c0);
        ql[kc][1] = *(const uint32_t*)(gq_lo + kbase + (size_t)qrow1 * HDD + c0);
        ql[kc][2] = *(const uint32_t*)(gq_lo + kbase + (size_t)qrow0 * HDD + c0 + 8);
        ql[kc][3] = *(const uint32_t*)(gq_lo + kbase + (size_t)qrow1 * HDD + c0 + 8);
    }

    int qri0 = (int)(((float)qrow0 + 0.5f) * invW);
    int qri1 = (int)(((float)qrow1 + 0.5f) * invW);
    const float qr0 = (float)qri0, qc0 = (float)(qrow0 - qri0 * Wg);
    const float qr1 = (float)qri1, qc1 = (float)(qrow1 - qri1 * Wg);

    float mg0 = -1e30f, lg0 = 0.f, mg1 = -1e30f, lg1 = 0.f;
    float accO[8][4];
#pragma unroll
    for (int ni = 0; ni < 8; ni++)
#pragma unroll
        for (int c = 0; c < 4; c++) accO[ni][c] = 0.f;

    load_tile(0, 0);

    for (int tk = 0; tk < 16; tk++) {
        const int s = tk & 1;
        const int k0 = tk << 6;
        cpa_wait<0>();
        __syncthreads();
        if (tk + 1 < 16) load_tile(tk + 1, s ^ 1);

        // ---- S = Q K^T (3 passes, ldmatrix B-frags) ----
        float S[8][4];
#pragma unroll
        for (int ni = 0; ni < 8; ni++)
#pragma unroll
            for (int c = 0; c < 4; c++) S[ni][c] = 0.f;

#pragma unroll
        for (int kc = 0; kc < 4; kc++) {
#pragma unroll
            for (int np = 0; np < 4; np++) {
                uint32_t bq[4];
                ldsm4(bq, Khi(s) + (np * 16 + b_r) * KPAD + kc * 16 + b_c);
                mma4(S[np * 2],     qh[kc], bq[0], bq[1]);
                mma4(S[np * 2],     ql[kc], bq[0], bq[1]);
                mma4(S[np * 2 + 1], qh[kc], bq[2], bq[3]);
                mma4(S[np * 2 + 1], ql[kc], bq[2], bq[3]);
                uint32_t cq[4];
                ldsm4(cq, Klo(s) + (np * 16 + b_r) * KPAD + kc * 16 + b_c);
                mma4(S[np * 2],     qh[kc], cq[0], cq[1]);
                mma4(S[np * 2 + 1], qh[kc], cq[2], cq[3]);
            }
        }

        // ---- bias ----
#pragma unroll
        for (int ni = 0; ni < 8; ni++) {
            int kA = k0 + ni * 8 + 2 * t;
            int kB = kA + 1;
            int krAi = (int)(((float)kA + 0.5f) * invW);
            int krBi = (int)(((float)kB + 0.5f) * invW);
            float krA = (float)krAi, kcA = (float)(kA - krAi * Wg);
            float krB = (float)krBi, kcB = (float)(kB - krBi * Wg);
            float dA0 = fabsf(qr0 - krA) + fabsf(qc0 - kcA);
            float dB0 = fabsf(qr0 - krB) + fabsf(qc0 - kcB);
            float dA1 = fabsf(qr1 - krA) + fabsf(qc1 - kcA);
            float dB1 = fabsf(qr1 - krB) + fabsf(qc1 - kcB);
            S[ni][0] = fmaf(S[ni][0], scale, -decay * dA0);
            S[ni][1] = fmaf(S[ni][1], scale, -decay * dB0);
            S[ni][2] = fmaf(S[ni][2], scale, -decay * dA1);
            S[ni][3] = fmaf(S[ni][3], scale, -decay * dB1);
        }

        // ---- online softmax ----
        float mx0 = -1e30f, mx1 = -1e30f;
#pragma unroll
        for (int ni = 0; ni < 8; ni++) {
            mx0 = fmaxf(mx0, fmaxf(S[ni][0], S[ni][1]));
            mx1 = fmaxf(mx1, fmaxf(S[ni][2], S[ni][3]));
        }
        mx0 = fmaxf(mx0, __shfl_xor_sync(0xffffffffu, mx0, 1));
        mx0 = fmaxf(mx0, __shfl_xor_sync(0xffffffffu, mx0, 2));
        mx1 = fmaxf(mx1, __shfl_xor_sync(0xffffffffu, mx1, 1));
        mx1 = fmaxf(mx1, __shfl_xor_sync(0xffffffffu, mx1, 2));
        float nm0 = fmaxf(mg0, mx0), nm1 = fmaxf(mg1, mx1);
        float al0 = __expf(mg0 - nm0), al1 = __expf(mg1 - nm1);
        float sum0 = 0.f, sum1 = 0.f;
#pragma unroll
        for (int ni = 0; ni < 8; ni++) {
            S[ni][0] = __expf(S[ni][0] - nm0); sum0 += S[ni][0];
            S[ni][1] = __expf(S[ni][1] - nm0); sum0 += S[ni][1];
            S[ni][2] = __expf(S[ni][2] - nm1); sum1 += S[ni][2];
            S[ni][3] = __expf(S[ni][3] - nm1); sum1 += S[ni][3];
        }
        sum0 += __shfl_xor_sync(0xffffffffu, sum0, 1);
        sum0 += __shfl_xor_sync(0xffffffffu, sum0, 2);
        sum1 += __shfl_xor_sync(0xffffffffu, sum1, 1);
        sum1 += __shfl_xor_sync(0xffffffffu, sum1, 2);
        lg0 = lg0 * al0 + sum0;  mg0 = nm0;
        lg1 = lg1 * al1 + sum1;  mg1 = nm1;
#pragma unroll
        for (int ni = 0; ni < 8; ni++) {
            accO[ni][0] *= al0; accO[ni][1] *= al0;
            accO[ni][2] *= al1; accO[ni][3] *= al1;
        }

        // ---- O += P V (ldmatrix V-frags) ----
#pragma unroll
        for (int kc = 0; kc < 4; kc++) {
            const int nA = 2 * kc, nB = 2 * kc + 1;
            uint32_t ph[4], pl[4];
            split2(S[nA][0], S[nA][1], ph[0], pl[0]);
            split2(S[nA][2], S[nA][3], ph[1], pl[1]);
            split2(S[nB][0], S[nB][1], ph[2], pl[2]);
            split2(S[nB][2], S[nB][3], ph[3], pl[3]);
#pragma unroll
            for (int np = 0; np < 4; np++) {
                uint32_t vq[4];
                ldsm4(vq, Vhi(s) + (np * 16 + b_r) * KPAD + kc * 16 + b_c);
                mma4(accO[np * 2],     ph, vq[0], vq[1]);
                mma4(accO[np * 2],     pl, vq[0], vq[1]);
                mma4(accO[np * 2 + 1], ph, vq[2], vq[3]);
                mma4(accO[np * 2 + 1], pl, vq[2], vq[3]);
                uint32_t wq[4];
                ldsm4(wq, Vlo(s) + (np * 16 + b_r) * KPAD + kc * 16 + b_c);
                mma4(accO[np * 2],     ph, wq[0], wq[1]);
                mma4(accO[np * 2 + 1], ph, wq[2], wq[3]);
            }
        }
        __syncthreads();
    }

    // ---- epilogue ----
    const float inv0 = 1.f / lg0;
    const float inv1 = 1.f / lg1;
#pragma unroll
    for (int ni = 0; ni < 8; ni++) {
        int d = ni * 8 + 2 * t;
        uint32_t hiA, loA, hiB, loB;
        split2(accO[ni][0] * inv0, accO[ni][1] * inv0, hiA, loA);
        split2(accO[ni][2] * inv1, accO[ni][3] * inv1, hiB, loB);
        size_t o0 = ((size_t)(b * NN + qrow0)) * DIMC + h * HDD + d;
        size_t o1 = ((size_t)(b * NN + qrow1)) * DIMC + h * HDD + d;
        *(uint32_t*)(go_hi + o0) = hiA;
        *(uint32_t*)(go_lo + o0) = loA;
        *(uint32_t*)(go_hi + o1) = hiB;
        *(uint32_t*)(go_lo + o1) = loB;
    }
}

// ---------------------------------------------------------------------------
extern "C" void kernel_launch(void* const* d_in, const int* in_sizes, int n_in,
                              void* d_out, int out_size)
{
    const float* x      = (const float*)d_in[0];
    const float* w_qkv  = (const float*)d_in[1];
    const float* w_proj = (const float*)d_in[2];
    const float* logd   = (const float*)d_in[3];
    const int*   pW     = (n_in > 5) ? (const int*)d_in[5] : nullptr;
    float* out = (float*)d_out;

    cudaFuncSetAttribute(hgemm_k<0>, cudaFuncAttributeMaxDynamicSharedMemorySize, SMEM_BYTES);
    cudaFuncSetAttribute(hgemm_k<1>, cudaFuncAttributeMaxDynamicSharedMemorySize, SMEM_BYTES);
    cudaFuncSetAttribute(attn_k, cudaFuncAttributeMaxDynamicSharedMemorySize, ATTN_SMEM);

    cvt_k<0><<<(MTOT * DIMC / 4 + 255) / 256, 256>>>(x, MTOT * DIMC);
    cvt_k<1><<<(3 * DIMC * DIMC / 4 + 255) / 256, 256>>>(w_qkv, 3 * DIMC * DIMC);
    cvt_k<2><<<(DIMC * DIMC / 4 + 255) / 256, 256>>>(w_proj, DIMC * DIMC);

    hgemm_k<0><<<dim3(12, 64), 256, SMEM_BYTES>>>(nullptr);
    attn_k<<<dim3(8, 64), 256, ATTN_SMEM>>>(logd, pW);
    hgemm_k<1><<<dim3(4, 64), 256, SMEM_BYTES>>>(out);
}

// round 11
// speedup vs baseline: 5.0935x; 1.3367x over previous
#include <cuda_runtime.h>
#include <cuda_bf16.h>
#include <cuda_fp16.h>
#include <cstdint>
#include <math.h>

#define DIMC 512
#define NHD  8
#define HDD  64
#define BB   8
#define NN   1024
#define MTOT (BB*NN)   // 8192
#define QKV  (BB*NHD*NN*HDD)

// ---------------- scratch (allocation-free) ----------------
__device__ __align__(16) __nv_bfloat16 gx_hi[MTOT*DIMC],  gx_lo[MTOT*DIMC];
__device__ __align__(16) __nv_bfloat16 gwq_hi[3*DIMC*DIMC], gwq_lo[3*DIMC*DIMC];
__device__ __align__(16) __nv_bfloat16 gwp_hi[DIMC*DIMC],  gwp_lo[DIMC*DIMC];
__device__ __align__(16) __half gqh[QKV];    // [bh][n][d]  fp16
__device__ __align__(16) __half gkh[QKV];    // [bh][n][d]  fp16
__device__ __align__(16) __half gvth[QKV];   // [bh][d][n]  fp16 (transposed)
__device__ __align__(16) __nv_bfloat16 go_hi[MTOT*DIMC], go_lo[MTOT*DIMC];

// ---------------- fp32 -> bf16 hi/lo split ----------------
template<int DST>
__global__ void cvt_k(const float* __restrict__ s, int n)
{
    __nv_bfloat16* hi;
    __nv_bfloat16* lo;
    if (DST == 0)      { hi = gx_hi;  lo = gx_lo;  }
    else if (DST == 1) { hi = gwq_hi; lo = gwq_lo; }
    else               { hi = gwp_hi; lo = gwp_lo; }

    int i = (blockIdx.x * blockDim.x + threadIdx.x) * 4;
    if (i >= n) return;
    float4 v = *(const float4*)(s + i);
    __nv_bfloat16 h0 = __float2bfloat16(v.x);
    __nv_bfloat16 h1 = __float2bfloat16(v.y);
    __nv_bfloat16 h2 = __float2bfloat16(v.z);
    __nv_bfloat16 h3 = __float2bfloat16(v.w);
    __nv_bfloat162 hp0; hp0.x = h0; hp0.y = h1;
    __nv_bfloat162 hp1; hp1.x = h2; hp1.y = h3;
    __nv_bfloat162 lp0;
    lp0.x = __float2bfloat16(v.x - __bfloat162float(h0));
    lp0.y = __float2bfloat16(v.y - __bfloat162float(h1));
    __nv_bfloat162 lp1;
    lp1.x = __float2bfloat16(v.z - __bfloat162float(h2));
    lp1.y = __float2bfloat16(v.w - __bfloat162float(h3));
    *(__nv_bfloat162*)(hi + i)     = hp0;
    *(__nv_bfloat162*)(hi + i + 2) = hp1;
    *(__nv_bfloat162*)(lo + i)     = lp0;
    *(__nv_bfloat162*)(lo + i + 2) = lp1;
}

// ---------------- helpers ----------------
__device__ __forceinline__ void mma4(float* c, const uint32_t* a,
                                     uint32_t b0, uint32_t b1)
{
    asm volatile(
        "mma.sync.aligned.m16n8k16.row.col.f32.bf16.bf16.f32 "
        "{%0,%1,%2,%3}, {%4,%5,%6,%7}, {%8,%9}, {%0,%1,%2,%3};"
        : "+f"(c[0]), "+f"(c[1]), "+f"(c[2]), "+f"(c[3])
        : "r"(a[0]), "r"(a[1]), "r"(a[2]), "r"(a[3]), "r"(b0), "r"(b1));
}

__device__ __forceinline__ void mma4h(float* c, const uint32_t* a,
                                      uint32_t b0, uint32_t b1)
{
    asm volatile(
        "mma.sync.aligned.m16n8k16.row.col.f32.f16.f16.f32 "
        "{%0,%1,%2,%3}, {%4,%5,%6,%7}, {%8,%9}, {%0,%1,%2,%3};"
        : "+f"(c[0]), "+f"(c[1]), "+f"(c[2]), "+f"(c[3])
        : "r"(a[0]), "r"(a[1]), "r"(a[2]), "r"(a[3]), "r"(b0), "r"(b1));
}

__device__ __forceinline__ void ldsm4(uint32_t* r, const void* p)
{
    uint32_t a = (uint32_t)__cvta_generic_to_shared(p);
    asm volatile("ldmatrix.sync.aligned.m8n8.x4.shared.b16 {%0,%1,%2,%3}, [%4];"
                 : "=r"(r[0]), "=r"(r[1]), "=r"(r[2]), "=r"(r[3]) : "r"(a));
}

__device__ __forceinline__ void split2(float v0, float v1,
                                       uint32_t& hi, uint32_t& lo)
{
    __nv_bfloat16 hx = __float2bfloat16(v0);
    __nv_bfloat16 hy = __float2bfloat16(v1);
    __nv_bfloat162 hp; hp.x = hx; hp.y = hy;
    hi = *(uint32_t*)&hp;
    __nv_bfloat162 lp;
    lp.x = __float2bfloat16(v0 - __bfloat162float(hx));
    lp.y = __float2bfloat16(v1 - __bfloat162float(hy));
    lo = *(uint32_t*)&lp;
}

__device__ __forceinline__ uint32_t packh2(float v0, float v1)
{
    __half2 hp = __floats2half2_rn(v0, v1);
    return *(uint32_t*)&hp;
}

__device__ __forceinline__ void cpa16(void* smem, const void* gmem)
{
    uint32_t s = (uint32_t)__cvta_generic_to_shared(smem);
    asm volatile("cp.async.ca.shared.global [%0], [%1], 16;"
                 :: "r"(s), "l"(gmem));
}
__device__ __forceinline__ void cpa_commit()
{ asm volatile("cp.async.commit_group;" ::: "memory"); }
template<int N>
__device__ __forceinline__ void cpa_wait()
{ asm volatile("cp.async.wait_group %0;" :: "n"(N) : "memory"); }

// ---------------------------------------------------------------------------
// HMMA GEMM — validated R9/R10 mainloop (3-stage cp.async, 128x128, ldmatrix).
// MODE 0 epilogue now emits fp16 q/k (and fp16 transposed v).
// ---------------------------------------------------------------------------
#define LDA_S 40
#define NCHUNK 48
#define STAGE_E (2 * 128 * LDA_S)
#define SMEM_BYTES (3 * STAGE_E * 2)

template<int MODE>
__global__ __launch_bounds__(256, 2)
void hgemm_k(float* __restrict__ Cout)
{
    extern __shared__ __align__(16) __nv_bfloat16 smem[];

    const int tid = threadIdx.x;
    const int wid = tid >> 5, lane = tid & 31;
    const int g = lane >> 2, t = lane & 3;
    const int m0 = blockIdx.y << 7;
    const int n0 = blockIdx.x << 7;
    const int wm = (wid & 3) << 5;
    const int wn = (wid >> 2) << 6;

    const __nv_bfloat16* a_hi = (MODE == 0) ? gx_hi : go_hi;
    const __nv_bfloat16* a_lo = (MODE == 0) ? gx_lo : go_lo;
    const __nv_bfloat16* b_hi = (MODE == 0) ? gwq_hi : gwp_hi;
    const __nv_bfloat16* b_lo = (MODE == 0) ? gwq_lo : gwp_lo;

    const int srow = tid >> 2, scu = (tid & 3) << 3;
    const int a_r = (lane & 7) + ((lane >> 3) & 1) * 8;
    const int a_c = (lane >> 4) * 8;
    const int b_r = (lane & 7) + (lane >> 4) * 8;
    const int b_c = ((lane >> 3) & 1) * 8;

    auto As = [&](int s) { return smem + s * STAGE_E; };
    auto Bs = [&](int s) { return smem + s * STAGE_E + 128 * LDA_S; };

    auto load_chunk = [&](int c, int s) {
        const int pass = c >> 4;
        const int kc = (c & 15) << 5;
        const __nv_bfloat16* asrc = (pass == 1) ? a_lo : a_hi;
        const __nv_bfloat16* bsrc = (pass == 2) ? b_lo : b_hi;
        __nv_bfloat16* as_ = As(s);
        __nv_bfloat16* bs_ = Bs(s);
#pragma unroll
        for (int i = 0; i < 2; i++) {
            int row = srow + (i << 6);
            cpa16(as_ + row * LDA_S + scu,
                  asrc + (size_t)(m0 + row) * DIMC + kc + scu);
            cpa16(bs_ + row * LDA_S + scu,
                  bsrc + (size_t)(n0 + row) * DIMC + kc + scu);
        }
        cpa_commit();
    };

    float acc[2][8][4];
#pragma unroll
    for (int mi = 0; mi < 2; mi++)
#pragma unroll
        for (int ni = 0; ni < 8; ni++)
#pragma unroll
            for (int c = 0; c < 4; c++) acc[mi][ni][c] = 0.f;

    load_chunk(0, 0);
    load_chunk(1, 1);

    for (int c = 0; c < NCHUNK; c++) {
        const int s = c % 3;
        if (c + 1 < NCHUNK) cpa_wait<1>(); else cpa_wait<0>();
        __syncthreads();
        if (c + 2 < NCHUNK) load_chunk(c + 2, (c + 2) % 3);

        const __nv_bfloat16* Ab = As(s);
        const __nv_bfloat16* Bb = Bs(s);
#pragma unroll
        for (int ks = 0; ks < 2; ks++) {
            const int k0 = ks << 4;
            uint32_t af[2][4];
            ldsm4(af[0], Ab + (wm + a_r) * LDA_S + k0 + a_c);
            ldsm4(af[1], Ab + (wm + 16 + a_r) * LDA_S + k0 + a_c);
#pragma unroll
            for (int np = 0; np < 4; np++) {
                uint32_t bq[4];
                ldsm4(bq, Bb + (wn + np * 16 + b_r) * LDA_S + k0 + b_c);
                mma4(acc[0][np * 2],     af[0], bq[0], bq[1]);
                mma4(acc[1][np * 2],     af[1], bq[0], bq[1]);
                mma4(acc[0][np * 2 + 1], af[0], bq[2], bq[3]);
                mma4(acc[1][np * 2 + 1], af[1], bq[2], bq[3]);
            }
        }
    }

    if (MODE == 0) {
#pragma unroll
        for (int mi = 0; mi < 2; mi++)
#pragma unroll
            for (int ni = 0; ni < 8; ni++) {
                int gm  = m0 + wm + (mi << 4) + g;
                int gm2 = gm + 8;
                int col = n0 + wn + (ni << 3) + 2 * t;
                int which = col >> 9;
                int h = (col >> 6) & (NHD - 1);
                int d = col & (HDD - 1);
                int b1_ = gm >> 10,  n1_ = gm & (NN - 1);
                int b2_ = gm2 >> 10, n2_ = gm2 & (NN - 1);
                if (which == 2) {
                    size_t vb1 = ((size_t)((b1_ * NHD + h) * HDD + d)) * NN + n1_;
                    gvth[vb1]      = __float2half_rn(acc[mi][ni][0]);
                    gvth[vb1 + NN] = __float2half_rn(acc[mi][ni][1]);
                    size_t vb2 = ((size_t)((b2_ * NHD + h) * HDD + d)) * NN + n2_;
                    gvth[vb2]      = __float2half_rn(acc[mi][ni][2]);
                    gvth[vb2 + NN] = __float2half_rn(acc[mi][ni][3]);
                } else {
                    __half* dst = which ? gkh : gqh;
                    size_t qb1 = ((size_t)((b1_ * NHD + h) * NN + n1_)) * HDD + d;
                    *(uint32_t*)(dst + qb1) = packh2(acc[mi][ni][0], acc[mi][ni][1]);
                    size_t qb2 = ((size_t)((b2_ * NHD + h) * NN + n2_)) * HDD + d;
                    *(uint32_t*)(dst + qb2) = packh2(acc[mi][ni][2], acc[mi][ni][3]);
                }
            }
    } else {
#pragma unroll
        for (int mi = 0; mi < 2; mi++)
#pragma unroll
            for (int ni = 0; ni < 8; ni++) {
                int gm = m0 + wm + (mi << 4) + g;
                int cc = n0 + wn + (ni << 3) + 2 * t;
                *(float2*)(Cout + (size_t)gm * DIMC + cc) =
                    make_float2(acc[mi][ni][0], acc[mi][ni][1]);
                *(float2*)(Cout + (size_t)(gm + 8) * DIMC + cc) =
                    make_float2(acc[mi][ni][2], acc[mi][ni][3]);
            }
    }
}

// ---------------------------------------------------------------------------
// Tensor-core flash attention, R11: single-pass fp16 QK and PV.
// 2-stage cp.async K/V pipeline + ldmatrix (layouts identical to R10).
// Softmax/bias fully fp32 (bias dominates logits and is exact).
// ---------------------------------------------------------------------------
#define KPAD 72
#define TILE_E (64 * KPAD)         // one array (K or V)
#define ASTAGE (2 * TILE_E)        // K, V per stage
#define ATTN_SMEM (2 * ASTAGE * 2) // 36864 bytes

__global__ __launch_bounds__(256, 2)
void attn_k(const float* __restrict__ logd, const int* __restrict__ pW)
{
    extern __shared__ __align__(16) __half asmem[];

    const int bh = blockIdx.y;
    const int b = bh >> 3, h = bh & 7;
    const int q0 = blockIdx.x << 7;
    const int tid = threadIdx.x;
    const int wid = tid >> 5, lane = tid & 31;
    const int g = lane >> 2, t = lane & 3;
    const int b_r = (lane & 7) + (lane >> 4) * 8;
    const int b_c = ((lane >> 3) & 1) * 8;

    const int Wg = pW ? *pW : 32;
    const float invW = 1.0f / (float)Wg;
    const float decay = log1pf(expf(logd[h]));
    const float scale = 0.125f;

    const size_t kbase = (size_t)bh * NN * HDD;

    auto Kh = [&](int s) { return asmem + s * ASTAGE; };
    auto Vh = [&](int s) { return asmem + s * ASTAGE + TILE_E; };

    auto load_tile = [&](int tk, int s) {
        const int k0 = tk << 6;
#pragma unroll
        for (int i = 0; i < 2; i++) {
            int idx = tid + (i << 8);
            int row = idx >> 3, cu = (idx & 7) << 3;
            cpa16(Kh(s) + row * KPAD + cu,
                  gkh + kbase + (size_t)(k0 + row) * HDD + cu);
            cpa16(Vh(s) + row * KPAD + cu,
                  gvth + kbase + (size_t)row * NN + k0 + cu);
        }
        cpa_commit();
    };

    // ---- preload Q fragments (fp16) straight from gmem ----
    const int qrow0 = q0 + (wid << 4) + g;
    const int qrow1 = qrow0 + 8;
    uint32_t qh[4][4];
#pragma unroll
    for (int kc = 0; kc < 4; kc++) {
        int c0 = kc * 16 + 2 * t;
        qh[kc][0] = *(const uint32_t*)(gqh + kbase + (size_t)qrow0 * HDD + c0);
        qh[kc][1] = *(const uint32_t*)(gqh + kbase + (size_t)qrow1 * HDD + c0);
        qh[kc][2] = *(const uint32_t*)(gqh + kbase + (size_t)qrow0 * HDD + c0 + 8);
        qh[kc][3] = *(const uint32_t*)(gqh + kbase + (size_t)qrow1 * HDD + c0 + 8);
    }

    int qri0 = (int)(((float)qrow0 + 0.5f) * invW);
    int qri1 = (int)(((float)qrow1 + 0.5f) * invW);
    const float qr0 = (float)qri0, qc0 = (float)(qrow0 - qri0 * Wg);
    const float qr1 = (float)qri1, qc1 = (float)(qrow1 - qri1 * Wg);

    float mg0 = -1e30f, lg0 = 0.f, mg1 = -1e30f, lg1 = 0.f;
    float accO[8][4];
#pragma unroll
    for (int ni = 0; ni < 8; ni++)
#pragma unroll
        for (int c = 0; c < 4; c++) accO[ni][c] = 0.f;

    load_tile(0, 0);

    for (int tk = 0; tk < 16; tk++) {
        const int s = tk & 1;
        const int k0 = tk << 6;
        cpa_wait<0>();
        __syncthreads();
        if (tk + 1 < 16) load_tile(tk + 1, s ^ 1);

        // ---- S = Q K^T (single fp16 pass) ----
        float S[8][4];
#pragma unroll
        for (int ni = 0; ni < 8; ni++)
#pragma unroll
            for (int c = 0; c < 4; c++) S[ni][c] = 0.f;

#pragma unroll
        for (int kc = 0; kc < 4; kc++) {
#pragma unroll
            for (int np = 0; np < 4; np++) {
                uint32_t bq[4];
                ldsm4(bq, Kh(s) + (np * 16 + b_r) * KPAD + kc * 16 + b_c);
                mma4h(S[np * 2],     qh[kc], bq[0], bq[1]);
                mma4h(S[np * 2 + 1], qh[kc], bq[2], bq[3]);
            }
        }

        // ---- bias ----
#pragma unroll
        for (int ni = 0; ni < 8; ni++) {
            int kA = k0 + ni * 8 + 2 * t;
            int kB = kA + 1;
            int krAi = (int)(((float)kA + 0.5f) * invW);
            int krBi = (int)(((float)kB + 0.5f) * invW);
            float krA = (float)krAi, kcA = (float)(kA - krAi * Wg);
            float krB = (float)krBi, kcB = (float)(kB - krBi * Wg);
            float dA0 = fabsf(qr0 - krA) + fabsf(qc0 - kcA);
            float dB0 = fabsf(qr0 - krB) + fabsf(qc0 - kcB);
            float dA1 = fabsf(qr1 - krA) + fabsf(qc1 - kcA);
            float dB1 = fabsf(qr1 - krB) + fabsf(qc1 - kcB);
            S[ni][0] = fmaf(S[ni][0], scale, -decay * dA0);
            S[ni][1] = fmaf(S[ni][1], scale, -decay * dB0);
            S[ni][2] = fmaf(S[ni][2], scale, -decay * dA1);
            S[ni][3] = fmaf(S[ni][3], scale, -decay * dB1);
        }

        // ---- online softmax (fp32) ----
        float mx0 = -1e30f, mx1 = -1e30f;
#pragma unroll
        for (int ni = 0; ni < 8; ni++) {
            mx0 = fmaxf(mx0, fmaxf(S[ni][0], S[ni][1]));
            mx1 = fmaxf(mx1, fmaxf(S[ni][2], S[ni][3]));
        }
        mx0 = fmaxf(mx0, __shfl_xor_sync(0xffffffffu, mx0, 1));
        mx0 = fmaxf(mx0, __shfl_xor_sync(0xffffffffu, mx0, 2));
        mx1 = fmaxf(mx1, __shfl_xor_sync(0xffffffffu, mx1, 1));
        mx1 = fmaxf(mx1, __shfl_xor_sync(0xffffffffu, mx1, 2));
        float nm0 = fmaxf(mg0, mx0), nm1 = fmaxf(mg1, mx1);
        float al0 = __expf(mg0 - nm0), al1 = __expf(mg1 - nm1);
        float sum0 = 0.f, sum1 = 0.f;
#pragma unroll
        for (int ni = 0; ni < 8; ni++) {
            S[ni][0] = __expf(S[ni][0] - nm0); sum0 += S[ni][0];
            S[ni][1] = __expf(S[ni][1] - nm0); sum0 += S[ni][1];
            S[ni][2] = __expf(S[ni][2] - nm1); sum1 += S[ni][2];
            S[ni][3] = __expf(S[ni][3] - nm1); sum1 += S[ni][3];
        }
        sum0 += __shfl_xor_sync(0xffffffffu, sum0, 1);
        sum0 += __shfl_xor_sync(0xffffffffu, sum0, 2);
        sum1 += __shfl_xor_sync(0xffffffffu, sum1, 1);
        sum1 += __shfl_xor_sync(0xffffffffu, sum1, 2);
        lg0 = lg0 * al0 + sum0;  mg0 = nm0;
        lg1 = lg1 * al1 + sum1;  mg1 = nm1;
#pragma unroll
        for (int ni = 0; ni < 8; ni++) {
            accO[ni][0] *= al0; accO[ni][1] *= al0;
            accO[ni][2] *= al1; accO[ni][3] *= al1;
        }

        // ---- O += P V (single fp16 pass) ----
#pragma unroll
        for (int kc = 0; kc < 4; kc++) {
            const int nA = 2 * kc, nB = 2 * kc + 1;
            uint32_t ph[4];
            ph[0] = packh2(S[nA][0], S[nA][1]);
            ph[1] = packh2(S[nA][2], S[nA][3]);
            ph[2] = packh2(S[nB][0], S[nB][1]);
            ph[3] = packh2(S[nB][2], S[nB][3]);
#pragma unroll
            for (int np = 0; np < 4; np++) {
                uint32_t vq[4];
                ldsm4(vq, Vh(s) + (np * 16 + b_r) * KPAD + kc * 16 + b_c);
                mma4h(accO[np * 2],     ph, vq[0], vq[1]);
                mma4h(accO[np * 2 + 1], ph, vq[2], vq[3]);
            }
        }
        // no barrier here: the next iteration's cpa_wait + __syncthreads
        // orders all stage reuse.
    }

    // ---- epilogue: O/l -> go_hi/go_lo (bf16 split for proj GEMM) ----
    const float inv0 = 1.f / lg0;
    const float inv1 = 1.f / lg1;
#pragma unroll
    for (int ni = 0; ni < 8; ni++) {
        int d = ni * 8 + 2 * t;
        uint32_t hiA, loA, hiB, loB;
        split2(accO[ni][0] * inv0, accO[ni][1] * inv0, hiA, loA);
        split2(accO[ni][2] * inv1, accO[ni][3] * inv1, hiB, loB);
        size_t o0 = ((size_t)(b * NN + qrow0)) * DIMC + h * HDD + d;
        size_t o1 = ((size_t)(b * NN + qrow1)) * DIMC + h * HDD + d;
        *(uint32_t*)(go_hi + o0) = hiA;
        *(uint32_t*)(go_lo + o0) = loA;
        *(uint32_t*)(go_hi + o1) = hiB;
        *(uint32_t*)(go_lo + o1) = loB;
    }
}

// ---------------------------------------------------------------------------
extern "C" void kernel_launch(void* const* d_in, const int* in_sizes, int n_in,
                              void* d_out, int out_size)
{
    const float* x      = (const float*)d_in[0];
    const float* w_qkv  = (const float*)d_in[1];
    const float* w_proj = (const float*)d_in[2];
    const float* logd   = (const float*)d_in[3];
    const int*   pW     = (n_in > 5) ? (const int*)d_in[5] : nullptr;
    float* out = (float*)d_out;

    cudaFuncSetAttribute(hgemm_k<0>, cudaFuncAttributeMaxDynamicSharedMemorySize, SMEM_BYTES);
    cudaFuncSetAttribute(hgemm_k<1>, cudaFuncAttributeMaxDynamicSharedMemorySize, SMEM_BYTES);
    cudaFuncSetAttribute(attn_k, cudaFuncAttributeMaxDynamicSharedMemorySize, ATTN_SMEM);

    cvt_k<0><<<(MTOT * DIMC / 4 + 255) / 256, 256>>>(x, MTOT * DIMC);
    cvt_k<1><<<(3 * DIMC * DIMC / 4 + 255) / 256, 256>>>(w_qkv, 3 * DIMC * DIMC);
    cvt_k<2><<<(DIMC * DIMC / 4 + 255) / 256, 256>>>(w_proj, DIMC * DIMC);

    hgemm_k<0><<<dim3(12, 64), 256, SMEM_BYTES>>>(nullptr);
    attn_k<<<dim3(8, 64), 256, ATTN_SMEM>>>(logd, pW);
    hgemm_k<1><<<dim3(4, 64), 256, SMEM_BYTES>>>(out);
}

// round 12
// speedup vs baseline: 8.8340x; 1.7344x over previous
#include <cuda_runtime.h>
#include <cuda_bf16.h>
#include <cuda_fp16.h>
#include <cstdint>
#include <math.h>

#define DIMC 512
#define NHD  8
#define HDD  64
#define BB   8
#define NN   1024
#define MTOT (BB*NN)   // 8192
#define QKV  (BB*NHD*NN*HDD)

// ---------------- scratch (allocation-free) ----------------
__device__ __align__(16) __half gxh[MTOT*DIMC];        // x   fp16
__device__ __align__(16) __half gwqh[3*DIMC*DIMC];     // w_qkv fp16
__device__ __align__(16) __half gwph[DIMC*DIMC];       // w_proj fp16
__device__ __align__(16) __half gqh[QKV];              // [bh][n][d]
__device__ __align__(16) __half gkh[QKV];              // [bh][n][d]
__device__ __align__(16) __half gvth[QKV];             // [bh][d][n] (transposed)
__device__ __align__(16) __half goh[MTOT*DIMC];        // attn out [b][n][c]

// ---------------- fp32 -> fp16 convert ----------------
template<int DST>
__global__ void cvt_k(const float* __restrict__ s, int n)
{
    __half* dst;
    if (DST == 0)      dst = gxh;
    else if (DST == 1) dst = gwqh;
    else               dst = gwph;

    int i = (blockIdx.x * blockDim.x + threadIdx.x) * 4;
    if (i >= n) return;
    float4 v = *(const float4*)(s + i);
    __half2 p0 = __floats2half2_rn(v.x, v.y);
    __half2 p1 = __floats2half2_rn(v.z, v.w);
    *(__half2*)(dst + i)     = p0;
    *(__half2*)(dst + i + 2) = p1;
}

// ---------------- helpers ----------------
__device__ __forceinline__ void mma4h(float* c, const uint32_t* a,
                                      uint32_t b0, uint32_t b1)
{
    asm volatile(
        "mma.sync.aligned.m16n8k16.row.col.f32.f16.f16.f32 "
        "{%0,%1,%2,%3}, {%4,%5,%6,%7}, {%8,%9}, {%0,%1,%2,%3};"
        : "+f"(c[0]), "+f"(c[1]), "+f"(c[2]), "+f"(c[3])
        : "r"(a[0]), "r"(a[1]), "r"(a[2]), "r"(a[3]), "r"(b0), "r"(b1));
}

__device__ __forceinline__ void ldsm4(uint32_t* r, const void* p)
{
    uint32_t a = (uint32_t)__cvta_generic_to_shared(p);
    asm volatile("ldmatrix.sync.aligned.m8n8.x4.shared.b16 {%0,%1,%2,%3}, [%4];"
                 : "=r"(r[0]), "=r"(r[1]), "=r"(r[2]), "=r"(r[3]) : "r"(a));
}

__device__ __forceinline__ uint32_t packh2(float v0, float v1)
{
    __half2 hp = __floats2half2_rn(v0, v1);
    return *(uint32_t*)&hp;
}

__device__ __forceinline__ void cpa16(void* smem, const void* gmem)
{
    uint32_t s = (uint32_t)__cvta_generic_to_shared(smem);
    asm volatile("cp.async.ca.shared.global [%0], [%1], 16;"
                 :: "r"(s), "l"(gmem));
}
__device__ __forceinline__ void cpa_commit()
{ asm volatile("cp.async.commit_group;" ::: "memory"); }
template<int N>
__device__ __forceinline__ void cpa_wait()
{ asm volatile("cp.async.wait_group %0;" :: "n"(N) : "memory"); }

// ---------------------------------------------------------------------------
// HMMA GEMM — single-pass fp16. 3-stage cp.async, 128x128 tile, ldmatrix.
// C[M,NC] = A[M,512] @ W[NC,512]^T. 8 warps = 4m x 2n; warp tile 32x64.
// MODE 0: A=x, W=w_qkv -> fp16 q/k (and transposed v). MODE 1: proj -> fp32.
// ---------------------------------------------------------------------------
#define LDA_S 40
#define NCHUNK 16
#define STAGE_E (2 * 128 * LDA_S)
#define SMEM_BYTES (3 * STAGE_E * 2)

template<int MODE>
__global__ __launch_bounds__(256, 2)
void hgemm_k(float* __restrict__ Cout)
{
    extern __shared__ __align__(16) __half smem[];

    const int tid = threadIdx.x;
    const int wid = tid >> 5, lane = tid & 31;
    const int g = lane >> 2, t = lane & 3;
    const int m0 = blockIdx.y << 7;
    const int n0 = blockIdx.x << 7;
    const int wm = (wid & 3) << 5;
    const int wn = (wid >> 2) << 6;

    const __half* asrc = (MODE == 0) ? gxh  : goh;
    const __half* bsrc = (MODE == 0) ? gwqh : gwph;

    const int srow = tid >> 2, scu = (tid & 3) << 3;
    const int a_r = (lane & 7) + ((lane >> 3) & 1) * 8;
    const int a_c = (lane >> 4) * 8;
    const int b_r = (lane & 7) + (lane >> 4) * 8;
    const int b_c = ((lane >> 3) & 1) * 8;

    auto As = [&](int s) { return smem + s * STAGE_E; };
    auto Bs = [&](int s) { return smem + s * STAGE_E + 128 * LDA_S; };

    auto load_chunk = [&](int c, int s) {
        const int kc = c << 5;
        __half* as_ = As(s);
        __half* bs_ = Bs(s);
#pragma unroll
        for (int i = 0; i < 2; i++) {
            int row = srow + (i << 6);
            cpa16(as_ + row * LDA_S + scu,
                  asrc + (size_t)(m0 + row) * DIMC + kc + scu);
            cpa16(bs_ + row * LDA_S + scu,
                  bsrc + (size_t)(n0 + row) * DIMC + kc + scu);
        }
        cpa_commit();
    };

    float acc[2][8][4];
#pragma unroll
    for (int mi = 0; mi < 2; mi++)
#pragma unroll
        for (int ni = 0; ni < 8; ni++)
#pragma unroll
            for (int c = 0; c < 4; c++) acc[mi][ni][c] = 0.f;

    load_chunk(0, 0);
    load_chunk(1, 1);

    for (int c = 0; c < NCHUNK; c++) {
        const int s = c % 3;
        if (c + 1 < NCHUNK) cpa_wait<1>(); else cpa_wait<0>();
        __syncthreads();
        if (c + 2 < NCHUNK) load_chunk(c + 2, (c + 2) % 3);

        const __half* Ab = As(s);
        const __half* Bb = Bs(s);
#pragma unroll
        for (int ks = 0; ks < 2; ks++) {
            const int k0 = ks << 4;
            uint32_t af[2][4];
            ldsm4(af[0], Ab + (wm + a_r) * LDA_S + k0 + a_c);
            ldsm4(af[1], Ab + (wm + 16 + a_r) * LDA_S + k0 + a_c);
#pragma unroll
            for (int np = 0; np < 4; np++) {
                uint32_t bq[4];
                ldsm4(bq, Bb + (wn + np * 16 + b_r) * LDA_S + k0 + b_c);
                mma4h(acc[0][np * 2],     af[0], bq[0], bq[1]);
                mma4h(acc[1][np * 2],     af[1], bq[0], bq[1]);
                mma4h(acc[0][np * 2 + 1], af[0], bq[2], bq[3]);
                mma4h(acc[1][np * 2 + 1], af[1], bq[2], bq[3]);
            }
        }
    }

    if (MODE == 0) {
#pragma unroll
        for (int mi = 0; mi < 2; mi++)
#pragma unroll
            for (int ni = 0; ni < 8; ni++) {
                int gm  = m0 + wm + (mi << 4) + g;
                int gm2 = gm + 8;
                int col = n0 + wn + (ni << 3) + 2 * t;
                int which = col >> 9;
                int h = (col >> 6) & (NHD - 1);
                int d = col & (HDD - 1);
                int b1_ = gm >> 10,  n1_ = gm & (NN - 1);
                int b2_ = gm2 >> 10, n2_ = gm2 & (NN - 1);
                if (which == 2) {
                    size_t vb1 = ((size_t)((b1_ * NHD + h) * HDD + d)) * NN + n1_;
                    gvth[vb1]      = __float2half_rn(acc[mi][ni][0]);
                    gvth[vb1 + NN] = __float2half_rn(acc[mi][ni][1]);
                    size_t vb2 = ((size_t)((b2_ * NHD + h) * HDD + d)) * NN + n2_;
                    gvth[vb2]      = __float2half_rn(acc[mi][ni][2]);
                    gvth[vb2 + NN] = __float2half_rn(acc[mi][ni][3]);
                } else {
                    __half* dst = which ? gkh : gqh;
                    size_t qb1 = ((size_t)((b1_ * NHD + h) * NN + n1_)) * HDD + d;
                    *(uint32_t*)(dst + qb1) = packh2(acc[mi][ni][0], acc[mi][ni][1]);
                    size_t qb2 = ((size_t)((b2_ * NHD + h) * NN + n2_)) * HDD + d;
                    *(uint32_t*)(dst + qb2) = packh2(acc[mi][ni][2], acc[mi][ni][3]);
                }
            }
    } else {
#pragma unroll
        for (int mi = 0; mi < 2; mi++)
#pragma unroll
            for (int ni = 0; ni < 8; ni++) {
                int gm = m0 + wm + (mi << 4) + g;
                int cc = n0 + wn + (ni << 3) + 2 * t;
                *(float2*)(Cout + (size_t)gm * DIMC + cc) =
                    make_float2(acc[mi][ni][0], acc[mi][ni][1]);
                *(float2*)(Cout + (size_t)(gm + 8) * DIMC + cc) =
                    make_float2(acc[mi][ni][2], acc[mi][ni][3]);
            }
    }
}

// ---------------------------------------------------------------------------
// Tensor-core flash attention — validated R11 (fp16 single-pass), epilogue
// now writes fp16 goh directly.
// ---------------------------------------------------------------------------
#define KPAD 72
#define TILE_E (64 * KPAD)
#define ASTAGE (2 * TILE_E)
#define ATTN_SMEM (2 * ASTAGE * 2) // 36864 bytes

__global__ __launch_bounds__(256, 2)
void attn_k(const float* __restrict__ logd, const int* __restrict__ pW)
{
    extern __shared__ __align__(16) __half asmem[];

    const int bh = blockIdx.y;
    const int b = bh >> 3, h = bh & 7;
    const int q0 = blockIdx.x << 7;
    const int tid = threadIdx.x;
    const int wid = tid >> 5, lane = tid & 31;
    const int g = lane >> 2, t = lane & 3;
    const int b_r = (lane & 7) + (lane >> 4) * 8;
    const int b_c = ((lane >> 3) & 1) * 8;

    const int Wg = pW ? *pW : 32;
    const float invW = 1.0f / (float)Wg;
    const float decay = log1pf(expf(logd[h]));
    const float scale = 0.125f;

    const size_t kbase = (size_t)bh * NN * HDD;

    auto Kh = [&](int s) { return asmem + s * ASTAGE; };
    auto Vh = [&](int s) { return asmem + s * ASTAGE + TILE_E; };

    auto load_tile = [&](int tk, int s) {
        const int k0 = tk << 6;
#pragma unroll
        for (int i = 0; i < 2; i++) {
            int idx = tid + (i << 8);
            int row = idx >> 3, cu = (idx & 7) << 3;
            cpa16(Kh(s) + row * KPAD + cu,
                  gkh + kbase + (size_t)(k0 + row) * HDD + cu);
            cpa16(Vh(s) + row * KPAD + cu,
                  gvth + kbase + (size_t)row * NN + k0 + cu);
        }
        cpa_commit();
    };

    const int qrow0 = q0 + (wid << 4) + g;
    const int qrow1 = qrow0 + 8;
    uint32_t qh[4][4];
#pragma unroll
    for (int kc = 0; kc < 4; kc++) {
        int c0 = kc * 16 + 2 * t;
        qh[kc][0] = *(const uint32_t*)(gqh + kbase + (size_t)qrow0 * HDD + c0);
        qh[kc][1] = *(const uint32_t*)(gqh + kbase + (size_t)qrow1 * HDD + c0);
        qh[kc][2] = *(const uint32_t*)(gqh + kbase + (size_t)qrow0 * HDD + c0 + 8);
        qh[kc][3] = *(const uint32_t*)(gqh + kbase + (size_t)qrow1 * HDD + c0 + 8);
    }

    int qri0 = (int)(((float)qrow0 + 0.5f) * invW);
    int qri1 = (int)(((float)qrow1 + 0.5f) * invW);
    const float qr0 = (float)qri0, qc0 = (float)(qrow0 - qri0 * Wg);
    const float qr1 = (float)qri1, qc1 = (float)(qrow1 - qri1 * Wg);

    float mg0 = -1e30f, lg0 = 0.f, mg1 = -1e30f, lg1 = 0.f;
    float accO[8][4];
#pragma unroll
    for (int ni = 0; ni < 8; ni++)
#pragma unroll
        for (int c = 0; c < 4; c++) accO[ni][c] = 0.f;

    load_tile(0, 0);

    for (int tk = 0; tk < 16; tk++) {
        const int s = tk & 1;
        const int k0 = tk << 6;
        cpa_wait<0>();
        __syncthreads();
        if (tk + 1 < 16) load_tile(tk + 1, s ^ 1);

        float S[8][4];
#pragma unroll
        for (int ni = 0; ni < 8; ni++)
#pragma unroll
            for (int c = 0; c < 4; c++) S[ni][c] = 0.f;

#pragma unroll
        for (int kc = 0; kc < 4; kc++) {
#pragma unroll
            for (int np = 0; np < 4; np++) {
                uint32_t bq[4];
                ldsm4(bq, Kh(s) + (np * 16 + b_r) * KPAD + kc * 16 + b_c);
                mma4h(S[np * 2],     qh[kc], bq[0], bq[1]);
                mma4h(S[np * 2 + 1], qh[kc], bq[2], bq[3]);
            }
        }

#pragma unroll
        for (int ni = 0; ni < 8; ni++) {
            int kA = k0 + ni * 8 + 2 * t;
            int kB = kA + 1;
            int krAi = (int)(((float)kA + 0.5f) * invW);
            int krBi = (int)(((float)kB + 0.5f) * invW);
            float krA = (float)krAi, kcA = (float)(kA - krAi * Wg);
            float krB = (float)krBi, kcB = (float)(kB - krBi * Wg);
            float dA0 = fabsf(qr0 - krA) + fabsf(qc0 - kcA);
            float dB0 = fabsf(qr0 - krB) + fabsf(qc0 - kcB);
            float dA1 = fabsf(qr1 - krA) + fabsf(qc1 - kcA);
            float dB1 = fabsf(qr1 - krB) + fabsf(qc1 - kcB);
            S[ni][0] = fmaf(S[ni][0], scale, -decay * dA0);
            S[ni][1] = fmaf(S[ni][1], scale, -decay * dB0);
            S[ni][2] = fmaf(S[ni][2], scale, -decay * dA1);
            S[ni][3] = fmaf(S[ni][3], scale, -decay * dB1);
        }

        float mx0 = -1e30f, mx1 = -1e30f;
#pragma unroll
        for (int ni = 0; ni < 8; ni++) {
            mx0 = fmaxf(mx0, fmaxf(S[ni][0], S[ni][1]));
            mx1 = fmaxf(mx1, fmaxf(S[ni][2], S[ni][3]));
        }
        mx0 = fmaxf(mx0, __shfl_xor_sync(0xffffffffu, mx0, 1));
        mx0 = fmaxf(mx0, __shfl_xor_sync(0xffffffffu, mx0, 2));
        mx1 = fmaxf(mx1, __shfl_xor_sync(0xffffffffu, mx1, 1));
        mx1 = fmaxf(mx1, __shfl_xor_sync(0xffffffffu, mx1, 2));
        float nm0 = fmaxf(mg0, mx0), nm1 = fmaxf(mg1, mx1);
        float al0 = __expf(mg0 - nm0), al1 = __expf(mg1 - nm1);
        float sum0 = 0.f, sum1 = 0.f;
#pragma unroll
        for (int ni = 0; ni < 8; ni++) {
            S[ni][0] = __expf(S[ni][0] - nm0); sum0 += S[ni][0];
            S[ni][1] = __expf(S[ni][1] - nm0); sum0 += S[ni][1];
            S[ni][2] = __expf(S[ni][2] - nm1); sum1 += S[ni][2];
            S[ni][3] = __expf(S[ni][3] - nm1); sum1 += S[ni][3];
        }
        sum0 += __shfl_xor_sync(0xffffffffu, sum0, 1);
        sum0 += __shfl_xor_sync(0xffffffffu, sum0, 2);
        sum1 += __shfl_xor_sync(0xffffffffu, sum1, 1);
        sum1 += __shfl_xor_sync(0xffffffffu, sum1, 2);
        lg0 = lg0 * al0 + sum0;  mg0 = nm0;
        lg1 = lg1 * al1 + sum1;  mg1 = nm1;
#pragma unroll
        for (int ni = 0; ni < 8; ni++) {
            accO[ni][0] *= al0; accO[ni][1] *= al0;
            accO[ni][2] *= al1; accO[ni][3] *= al1;
        }

#pragma unroll
        for (int kc = 0; kc < 4; kc++) {
            const int nA = 2 * kc, nB = 2 * kc + 1;
            uint32_t ph[4];
            ph[0] = packh2(S[nA][0], S[nA][1]);
            ph[1] = packh2(S[nA][2], S[nA][3]);
            ph[2] = packh2(S[nB][0], S[nB][1]);
            ph[3] = packh2(S[nB][2], S[nB][3]);
#pragma unroll
            for (int np = 0; np < 4; np++) {
                uint32_t vq[4];
                ldsm4(vq, Vh(s) + (np * 16 + b_r) * KPAD + kc * 16 + b_c);
                mma4h(accO[np * 2],     ph, vq[0], vq[1]);
                mma4h(accO[np * 2 + 1], ph, vq[2], vq[3]);
            }
        }
    }

    const float inv0 = 1.f / lg0;
    const float inv1 = 1.f / lg1;
#pragma unroll
    for (int ni = 0; ni < 8; ni++) {
        int d = ni * 8 + 2 * t;
        size_t o0 = ((size_t)(b * NN + qrow0)) * DIMC + h * HDD + d;
        size_t o1 = ((size_t)(b * NN + qrow1)) * DIMC + h * HDD + d;
        *(uint32_t*)(goh + o0) = packh2(accO[ni][0] * inv0, accO[ni][1] * inv0);
        *(uint32_t*)(goh + o1) = packh2(accO[ni][2] * inv1, accO[ni][3] * inv1);
    }
}

// ---------------------------------------------------------------------------
extern "C" void kernel_launch(void* const* d_in, const int* in_sizes, int n_in,
                              void* d_out, int out_size)
{
    const float* x      = (const float*)d_in[0];
    const float* w_qkv  = (const float*)d_in[1];
    const float* w_proj = (const float*)d_in[2];
    const float* logd   = (const float*)d_in[3];
    const int*   pW     = (n_in > 5) ? (const int*)d_in[5] : nullptr;
    float* out = (float*)d_out;

    cudaFuncSetAttribute(hgemm_k<0>, cudaFuncAttributeMaxDynamicSharedMemorySize, SMEM_BYTES);
    cudaFuncSetAttribute(hgemm_k<1>, cudaFuncAttributeMaxDynamicSharedMemorySize, SMEM_BYTES);
    cudaFuncSetAttribute(attn_k, cudaFuncAttributeMaxDynamicSharedMemorySize, ATTN_SMEM);

    cvt_k<0><<<(MTOT * DIMC / 4 + 255) / 256, 256>>>(x, MTOT * DIMC);
    cvt_k<1><<<(3 * DIMC * DIMC / 4 + 255) / 256, 256>>>(w_qkv, 3 * DIMC * DIMC);
    cvt_k<2><<<(DIMC * DIMC / 4 + 255) / 256, 256>>>(w_proj, DIMC * DIMC);

    hgemm_k<0><<<dim3(12, 64), 256, SMEM_BYTES>>>(nullptr);
    attn_k<<<dim3(8, 64), 256, ATTN_SMEM>>>(logd, pW);
    hgemm_k<1><<<dim3(4, 64), 256, SMEM_BYTES>>>(out);
}

// round 13
// speedup vs baseline: 10.0906x; 1.1423x over previous
#include <cuda_runtime.h>
#include <cuda_bf16.h>
#include <cuda_fp16.h>
#include <cstdint>
#include <math.h>

#define DIMC 512
#define NHD  8
#define HDD  64
#define BB   8
#define NN   1024
#define MTOT (BB*NN)   // 8192
#define QKV  (BB*NHD*NN*HDD)

// ---------------- scratch (allocation-free) ----------------
__device__ __align__(16) __half gxh[MTOT*DIMC];        // x   fp16
__device__ __align__(16) __half gwqh[3*DIMC*DIMC];     // w_qkv fp16
__device__ __align__(16) __half gwph[DIMC*DIMC];       // w_proj fp16
__device__ __align__(16) __half gqh[QKV];              // [bh][n][d]
__device__ __align__(16) __half gkh[QKV];              // [bh][n][d]
__device__ __align__(16) __half gvth[QKV];             // [bh][d][n] (transposed)
__device__ __align__(16) __half goh[MTOT*DIMC];        // attn out [b][n][c]

// ---------------- fused fp32 -> fp16 convert (one launch) ----------------
#define CVT_N0 (MTOT*DIMC)
#define CVT_N1 (3*DIMC*DIMC)
#define CVT_N2 (DIMC*DIMC)
#define CVT_TOT (CVT_N0 + CVT_N1 + CVT_N2)

__global__ void cvtall_k(const float* __restrict__ x,
                         const float* __restrict__ wq,
                         const float* __restrict__ wp)
{
    int i = (blockIdx.x * blockDim.x + threadIdx.x) * 4;
    if (i >= CVT_TOT) return;
    const float* s;
    __half* dst;
    int off;
    if (i < CVT_N0)                { s = x;  dst = gxh;  off = i; }
    else if (i < CVT_N0 + CVT_N1)  { s = wq; dst = gwqh; off = i - CVT_N0; }
    else                           { s = wp; dst = gwph; off = i - CVT_N0 - CVT_N1; }
    float4 v = *(const float4*)(s + off);
    *(__half2*)(dst + off)     = __floats2half2_rn(v.x, v.y);
    *(__half2*)(dst + off + 2) = __floats2half2_rn(v.z, v.w);
}

// ---------------- helpers ----------------
__device__ __forceinline__ void mma4h(float* c, const uint32_t* a,
                                      uint32_t b0, uint32_t b1)
{
    asm volatile(
        "mma.sync.aligned.m16n8k16.row.col.f32.f16.f16.f32 "
        "{%0,%1,%2,%3}, {%4,%5,%6,%7}, {%8,%9}, {%0,%1,%2,%3};"
        : "+f"(c[0]), "+f"(c[1]), "+f"(c[2]), "+f"(c[3])
        : "r"(a[0]), "r"(a[1]), "r"(a[2]), "r"(a[3]), "r"(b0), "r"(b1));
}

__device__ __forceinline__ void ldsm4(uint32_t* r, const void* p)
{
    uint32_t a = (uint32_t)__cvta_generic_to_shared(p);
    asm volatile("ldmatrix.sync.aligned.m8n8.x4.shared.b16 {%0,%1,%2,%3}, [%4];"
                 : "=r"(r[0]), "=r"(r[1]), "=r"(r[2]), "=r"(r[3]) : "r"(a));
}

__device__ __forceinline__ uint32_t packh2(float v0, float v1)
{
    __half2 hp = __floats2half2_rn(v0, v1);
    return *(uint32_t*)&hp;
}

__device__ __forceinline__ void cpa16(void* smem, const void* gmem)
{
    uint32_t s = (uint32_t)__cvta_generic_to_shared(smem);
    asm volatile("cp.async.ca.shared.global [%0], [%1], 16;"
                 :: "r"(s), "l"(gmem));
}
__device__ __forceinline__ void cpa_commit()
{ asm volatile("cp.async.commit_group;" ::: "memory"); }
template<int N>
__device__ __forceinline__ void cpa_wait()
{ asm volatile("cp.async.wait_group %0;" :: "n"(N) : "memory"); }

// ---------------------------------------------------------------------------
// HMMA GEMM — fp16 single-pass. 2-stage cp.async pipeline, K-chunk 64,
// 128x128 tile, ldmatrix. 8 warps = 4m x 2n; warp tile 32x64.
// ---------------------------------------------------------------------------
#define GP 72                       // smem row stride (64 data + 8 pad)
#define NCHUNK 8
#define STAGE_E (2 * 128 * GP)
#define SMEM_BYTES (2 * STAGE_E * 2)   // 73728

template<int MODE>
__global__ __launch_bounds__(256, 2)
void hgemm_k(float* __restrict__ Cout)
{
    extern __shared__ __align__(16) __half smem[];

    const int tid = threadIdx.x;
    const int wid = tid >> 5, lane = tid & 31;
    const int g = lane >> 2, t = lane & 3;
    const int m0 = blockIdx.y << 7;
    const int n0 = blockIdx.x << 7;
    const int wm = (wid & 3) << 5;
    const int wn = (wid >> 2) << 6;

    const __half* asrc = (MODE == 0) ? gxh  : goh;
    const __half* bsrc = (MODE == 0) ? gwqh : gwph;

    const int a_r = (lane & 7) + ((lane >> 3) & 1) * 8;
    const int a_c = (lane >> 4) * 8;
    const int b_r = (lane & 7) + (lane >> 4) * 8;
    const int b_c = ((lane >> 3) & 1) * 8;

    auto As = [&](int s) { return smem + s * STAGE_E; };
    auto Bs = [&](int s) { return smem + s * STAGE_E + 128 * GP; };

    // staging: 128 rows x 8 units of 16B per array; 4 units/thread/array
    auto load_chunk = [&](int c, int s) {
        const int kc = c << 6;
        __half* as_ = As(s);
        __half* bs_ = Bs(s);
#pragma unroll
        for (int i = 0; i < 4; i++) {
            int idx = tid + (i << 8);
            int row = idx >> 3, cu = (idx & 7) << 3;
            cpa16(as_ + row * GP + cu,
                  asrc + (size_t)(m0 + row) * DIMC + kc + cu);
            cpa16(bs_ + row * GP + cu,
                  bsrc + (size_t)(n0 + row) * DIMC + kc + cu);
        }
        cpa_commit();
    };

    float acc[2][8][4];
#pragma unroll
    for (int mi = 0; mi < 2; mi++)
#pragma unroll
        for (int ni = 0; ni < 8; ni++)
#pragma unroll
            for (int c = 0; c < 4; c++) acc[mi][ni][c] = 0.f;

    load_chunk(0, 0);

    for (int c = 0; c < NCHUNK; c++) {
        const int s = c & 1;
        cpa_wait<0>();
        __syncthreads();
        if (c + 1 < NCHUNK) load_chunk(c + 1, s ^ 1);

        const __half* Ab = As(s);
        const __half* Bb = Bs(s);
#pragma unroll
        for (int ks = 0; ks < 4; ks++) {
            const int k0 = ks << 4;
            uint32_t af[2][4];
            ldsm4(af[0], Ab + (wm + a_r) * GP + k0 + a_c);
            ldsm4(af[1], Ab + (wm + 16 + a_r) * GP + k0 + a_c);
#pragma unroll
            for (int np = 0; np < 4; np++) {
                uint32_t bq[4];
                ldsm4(bq, Bb + (wn + np * 16 + b_r) * GP + k0 + b_c);
                mma4h(acc[0][np * 2],     af[0], bq[0], bq[1]);
                mma4h(acc[1][np * 2],     af[1], bq[0], bq[1]);
                mma4h(acc[0][np * 2 + 1], af[0], bq[2], bq[3]);
                mma4h(acc[1][np * 2 + 1], af[1], bq[2], bq[3]);
            }
        }
    }

    if (MODE == 0) {
#pragma unroll
        for (int mi = 0; mi < 2; mi++)
#pragma unroll
            for (int ni = 0; ni < 8; ni++) {
                int gm  = m0 + wm + (mi << 4) + g;
                int gm2 = gm + 8;
                int col = n0 + wn + (ni << 3) + 2 * t;
                int which = col >> 9;
                int h = (col >> 6) & (NHD - 1);
                int d = col & (HDD - 1);
                int b1_ = gm >> 10,  n1_ = gm & (NN - 1);
                int b2_ = gm2 >> 10, n2_ = gm2 & (NN - 1);
                if (which == 2) {
                    size_t vb1 = ((size_t)((b1_ * NHD + h) * HDD + d)) * NN + n1_;
                    gvth[vb1]      = __float2half_rn(acc[mi][ni][0]);
                    gvth[vb1 + NN] = __float2half_rn(acc[mi][ni][1]);
                    size_t vb2 = ((size_t)((b2_ * NHD + h) * HDD + d)) * NN + n2_;
                    gvth[vb2]      = __float2half_rn(acc[mi][ni][2]);
                    gvth[vb2 + NN] = __float2half_rn(acc[mi][ni][3]);
                } else {
                    __half* dst = which ? gkh : gqh;
                    size_t qb1 = ((size_t)((b1_ * NHD + h) * NN + n1_)) * HDD + d;
                    *(uint32_t*)(dst + qb1) = packh2(acc[mi][ni][0], acc[mi][ni][1]);
                    size_t qb2 = ((size_t)((b2_ * NHD + h) * NN + n2_)) * HDD + d;
                    *(uint32_t*)(dst + qb2) = packh2(acc[mi][ni][2], acc[mi][ni][3]);
                }
            }
    } else {
#pragma unroll
        for (int mi = 0; mi < 2; mi++)
#pragma unroll
            for (int ni = 0; ni < 8; ni++) {
                int gm = m0 + wm + (mi << 4) + g;
                int cc = n0 + wn + (ni << 3) + 2 * t;
                *(float2*)(Cout + (size_t)gm * DIMC + cc) =
                    make_float2(acc[mi][ni][0], acc[mi][ni][1]);
                *(float2*)(Cout + (size_t)(gm + 8) * DIMC + cc) =
                    make_float2(acc[mi][ni][2], acc[mi][ni][3]);
            }
    }
}

// ---------------------------------------------------------------------------
// Tensor-core flash attention (fp16 single-pass, validated R11/R12), with:
//  - log2-domain softmax (exp2f; identical probabilities)
//  - Wg==32 bias fast path: no per-tile int/float conversions
// ---------------------------------------------------------------------------
#define KPAD 72
#define TILE_E (64 * KPAD)
#define ASTAGE (2 * TILE_E)
#define ATTN_SMEM (2 * ASTAGE * 2) // 36864 bytes
#define LOG2E 1.4426950408889634f

__global__ __launch_bounds__(256, 2)
void attn_k(const float* __restrict__ logd, const int* __restrict__ pW)
{
    extern __shared__ __align__(16) __half asmem[];

    const int bh = blockIdx.y;
    const int b = bh >> 3, h = bh & 7;
    const int q0 = blockIdx.x << 7;
    const int tid = threadIdx.x;
    const int wid = tid >> 5, lane = tid & 31;
    const int g = lane >> 2, t = lane & 3;
    const int b_r = (lane & 7) + (lane >> 4) * 8;
    const int b_c = ((lane >> 3) & 1) * 8;

    const int Wg = pW ? *pW : 32;
    const float invW = 1.0f / (float)Wg;
    const float decay = log1pf(expf(logd[h]));
    const float scale2 = 0.125f * LOG2E;
    const float decay2 = decay * LOG2E;
    const bool fast = (Wg == 32);

    const size_t kbase = (size_t)bh * NN * HDD;

    auto Kh = [&](int s) { return asmem + s * ASTAGE; };
    auto Vh = [&](int s) { return asmem + s * ASTAGE + TILE_E; };

    auto load_tile = [&](int tk, int s) {
        const int k0 = tk << 6;
#pragma unroll
        for (int i = 0; i < 2; i++) {
            int idx = tid + (i << 8);
            int row = idx >> 3, cu = (idx & 7) << 3;
            cpa16(Kh(s) + row * KPAD + cu,
                  gkh + kbase + (size_t)(k0 + row) * HDD + cu);
            cpa16(Vh(s) + row * KPAD + cu,
                  gvth + kbase + (size_t)row * NN + k0 + cu);
        }
        cpa_commit();
    };

    const int qrow0 = q0 + (wid << 4) + g;
    const int qrow1 = qrow0 + 8;
    uint32_t qh[4][4];
#pragma unroll
    for (int kc = 0; kc < 4; kc++) {
        int c0 = kc * 16 + 2 * t;
        qh[kc][0] = *(const uint32_t*)(gqh + kbase + (size_t)qrow0 * HDD + c0);
        qh[kc][1] = *(const uint32_t*)(gqh + kbase + (size_t)qrow1 * HDD + c0);
        qh[kc][2] = *(const uint32_t*)(gqh + kbase + (size_t)qrow0 * HDD + c0 + 8);
        qh[kc][3] = *(const uint32_t*)(gqh + kbase + (size_t)qrow1 * HDD + c0 + 8);
    }

    int qri0 = (int)(((float)qrow0 + 0.5f) * invW);
    int qri1 = (int)(((float)qrow1 + 0.5f) * invW);
    const float qr0 = (float)qri0, qc0 = (float)(qrow0 - qri0 * Wg);
    const float qr1 = (float)qri1, qc1 = (float)(qrow1 - qri1 * Wg);

    // Wg==32 fast-path: per-(ni&3) column-distance bias terms, premultiplied
    float ccA0[4], ccB0[4], ccA1[4], ccB1[4];
    if (fast) {
#pragma unroll
        for (int j = 0; j < 4; j++) {
            float colA = (float)(j * 8 + 2 * t);
            float colB = colA + 1.f;
            ccA0[j] = -decay2 * fabsf(qc0 - colA);
            ccB0[j] = -decay2 * fabsf(qc0 - colB);
            ccA1[j] = -decay2 * fabsf(qc1 - colA);
            ccB1[j] = -decay2 * fabsf(qc1 - colB);
        }
    }

    float mg0 = -1e30f, lg0 = 0.f, mg1 = -1e30f, lg1 = 0.f;
    float accO[8][4];
#pragma unroll
    for (int ni = 0; ni < 8; ni++)
#pragma unroll
        for (int c = 0; c < 4; c++) accO[ni][c] = 0.f;

    load_tile(0, 0);

    for (int tk = 0; tk < 16; tk++) {
        const int s = tk & 1;
        const int k0 = tk << 6;
        cpa_wait<0>();
        __syncthreads();
        if (tk + 1 < 16) load_tile(tk + 1, s ^ 1);

        float S[8][4];
#pragma unroll
        for (int ni = 0; ni < 8; ni++)
#pragma unroll
            for (int c = 0; c < 4; c++) S[ni][c] = 0.f;

#pragma unroll
        for (int kc = 0; kc < 4; kc++) {
#pragma unroll
            for (int np = 0; np < 4; np++) {
                uint32_t bq[4];
                ldsm4(bq, Kh(s) + (np * 16 + b_r) * KPAD + kc * 16 + b_c);
                mma4h(S[np * 2],     qh[kc], bq[0], bq[1]);
                mma4h(S[np * 2 + 1], qh[kc], bq[2], bq[3]);
            }
        }

        // ---- bias (log2 domain) ----
        if (fast) {
            float kr0 = (float)(2 * tk), kr1 = kr0 + 1.f;
            float r00 = -decay2 * fabsf(qr0 - kr0);
            float r01 = -decay2 * fabsf(qr0 - kr1);
            float r10 = -decay2 * fabsf(qr1 - kr0);
            float r11 = -decay2 * fabsf(qr1 - kr1);
#pragma unroll
            for (int ni = 0; ni < 8; ni++) {
                int j = ni & 3;
                float rq0 = (ni >> 2) ? r01 : r00;
                float rq1 = (ni >> 2) ? r11 : r10;
                S[ni][0] = fmaf(S[ni][0], scale2, rq0 + ccA0[j]);
                S[ni][1] = fmaf(S[ni][1], scale2, rq0 + ccB0[j]);
                S[ni][2] = fmaf(S[ni][2], scale2, rq1 + ccA1[j]);
                S[ni][3] = fmaf(S[ni][3], scale2, rq1 + ccB1[j]);
            }
        } else {
#pragma unroll
            for (int ni = 0; ni < 8; ni++) {
                int kA = k0 + ni * 8 + 2 * t;
                int kB = kA + 1;
                int krAi = (int)(((float)kA + 0.5f) * invW);
                int krBi = (int)(((float)kB + 0.5f) * invW);
                float krA = (float)krAi, kcA = (float)(kA - krAi * Wg);
                float krB = (float)krBi, kcB = (float)(kB - krBi * Wg);
                float dA0 = fabsf(qr0 - krA) + fabsf(qc0 - kcA);
                float dB0 = fabsf(qr0 - krB) + fabsf(qc0 - kcB);
                float dA1 = fabsf(qr1 - krA) + fabsf(qc1 - kcA);
                float dB1 = fabsf(qr1 - krB) + fabsf(qc1 - kcB);
                S[ni][0] = fmaf(S[ni][0], scale2, -decay2 * dA0);
                S[ni][1] = fmaf(S[ni][1], scale2, -decay2 * dB0);
                S[ni][2] = fmaf(S[ni][2], scale2, -decay2 * dA1);
                S[ni][3] = fmaf(S[ni][3], scale2, -decay2 * dB1);
            }
        }

        // ---- online softmax (log2 domain; identical probabilities) ----
        float mx0 = -1e30f, mx1 = -1e30f;
#pragma unroll
        for (int ni = 0; ni < 8; ni++) {
            mx0 = fmaxf(mx0, fmaxf(S[ni][0], S[ni][1]));
            mx1 = fmaxf(mx1, fmaxf(S[ni][2], S[ni][3]));
        }
        mx0 = fmaxf(mx0, __shfl_xor_sync(0xffffffffu, mx0, 1));
        mx0 = fmaxf(mx0, __shfl_xor_sync(0xffffffffu, mx0, 2));
        mx1 = fmaxf(mx1, __shfl_xor_sync(0xffffffffu, mx1, 1));
        mx1 = fmaxf(mx1, __shfl_xor_sync(0xffffffffu, mx1, 2));
        float nm0 = fmaxf(mg0, mx0), nm1 = fmaxf(mg1, mx1);
        float al0 = exp2f(mg0 - nm0), al1 = exp2f(mg1 - nm1);
        float sum0 = 0.f, sum1 = 0.f;
#pragma unroll
        for (int ni = 0; ni < 8; ni++) {
            S[ni][0] = exp2f(S[ni][0] - nm0); sum0 += S[ni][0];
            S[ni][1] = exp2f(S[ni][1] - nm0); sum0 += S[ni][1];
            S[ni][2] = exp2f(S[ni][2] - nm1); sum1 += S[ni][2];
            S[ni][3] = exp2f(S[ni][3] - nm1); sum1 += S[ni][3];
        }
        sum0 += __shfl_xor_sync(0xffffffffu, sum0, 1);
        sum0 += __shfl_xor_sync(0xffffffffu, sum0, 2);
        sum1 += __shfl_xor_sync(0xffffffffu, sum1, 1);
        sum1 += __shfl_xor_sync(0xffffffffu, sum1, 2);
        lg0 = lg0 * al0 + sum0;  mg0 = nm0;
        lg1 = lg1 * al1 + sum1;  mg1 = nm1;
#pragma unroll
        for (int ni = 0; ni < 8; ni++) {
            accO[ni][0] *= al0; accO[ni][1] *= al0;
            accO[ni][2] *= al1; accO[ni][3] *= al1;
        }

#pragma unroll
        for (int kc = 0; kc < 4; kc++) {
            const int nA = 2 * kc, nB = 2 * kc + 1;
            uint32_t ph[4];
            ph[0] = packh2(S[nA][0], S[nA][1]);
            ph[1] = packh2(S[nA][2], S[nA][3]);
            ph[2] = packh2(S[nB][0], S[nB][1]);
            ph[3] = packh2(S[nB][2], S[nB][3]);
#pragma unroll
            for (int np = 0; np < 4; np++) {
                uint32_t vq[4];
                ldsm4(vq, Vh(s) + (np * 16 + b_r) * KPAD + kc * 16 + b_c);
                mma4h(accO[np * 2],     ph, vq[0], vq[1]);
                mma4h(accO[np * 2 + 1], ph, vq[2], vq[3]);
            }
        }
    }

    const float inv0 = 1.f / lg0;
    const float inv1 = 1.f / lg1;
#pragma unroll
    for (int ni = 0; ni < 8; ni++) {
        int d = ni * 8 + 2 * t;
        size_t o0 = ((size_t)(b * NN + qrow0)) * DIMC + h * HDD + d;
        size_t o1 = ((size_t)(b * NN + qrow1)) * DIMC + h * HDD + d;
        *(uint32_t*)(goh + o0) = packh2(accO[ni][0] * inv0, accO[ni][1] * inv0);
        *(uint32_t*)(goh + o1) = packh2(accO[ni][2] * inv1, accO[ni][3] * inv1);
    }
}

// ---------------------------------------------------------------------------
extern "C" void kernel_launch(void* const* d_in, const int* in_sizes, int n_in,
                              void* d_out, int out_size)
{
    const float* x      = (const float*)d_in[0];
    const float* w_qkv  = (const float*)d_in[1];
    const float* w_proj = (const float*)d_in[2];
    const float* logd   = (const float*)d_in[3];
    const int*   pW     = (n_in > 5) ? (const int*)d_in[5] : nullptr;
    float* out = (float*)d_out;

    cudaFuncSetAttribute(hgemm_k<0>, cudaFuncAttributeMaxDynamicSharedMemorySize, SMEM_BYTES);
    cudaFuncSetAttribute(hgemm_k<1>, cudaFuncAttributeMaxDynamicSharedMemorySize, SMEM_BYTES);
    cudaFuncSetAttribute(attn_k, cudaFuncAttributeMaxDynamicSharedMemorySize, ATTN_SMEM);

    cvtall_k<<<(CVT_TOT / 4 + 255) / 256, 256>>>(x, w_qkv, w_proj);
    hgemm_k<0><<<dim3(12, 64), 256, SMEM_BYTES>>>(nullptr);
    attn_k<<<dim3(8, 64), 256, ATTN_SMEM>>>(logd, pW);
    hgemm_k<1><<<dim3(4, 64), 256, SMEM_BYTES>>>(out);
}